// round 1
// baseline (speedup 1.0000x reference)
#include <cuda_runtime.h>

#define S_LEN 2048
#define EMB   1024
#define NH    16
#define HD    64
#define BATCH 2
#define MTOT  (BATCH * S_LEN)   // 4096

// Scratch (allocation-free: __device__ globals)
__device__ float g_qkv[(size_t)MTOT * 3 * EMB];  // [4096, 3072] : q|k|v
__device__ float g_ctx[(size_t)MTOT * EMB];      // [4096, 1024] : [B,S,H,D]

// ---------------------------------------------------------------------------
// SGEMM (NT): C[M,N] = A[M,K] * B[N,K]^T + bias[N]
// Both operands are K-contiguous row-major (torch Linear weight layout).
// 128x128 tile, BK=8, 256 threads, 8x8 per-thread microtile.
// A_==nullptr -> use g_ctx as A; C_==nullptr -> use g_qkv as C.
// ---------------------------------------------------------------------------
__global__ void __launch_bounds__(256) sgemm_nt_bias(
    const float* __restrict__ A_, const float* __restrict__ B,
    const float* __restrict__ bias, float* __restrict__ C_,
    int M, int N, int K)
{
    const float* A = A_ ? A_ : g_ctx;
    float* C = C_ ? C_ : g_qkv;

    const int BM = 128, BN = 128, BK = 8;
    __shared__ float As[BK][BM];
    __shared__ float Bs[BK][BN];

    const int t  = threadIdx.x;
    const int bm = blockIdx.y * BM;
    const int bn = blockIdx.x * BN;

    // global load mapping: each thread loads one float4 of A tile and one of B tile
    const int lrow = t >> 1;          // 0..127
    const int lcol = (t & 1) * 4;     // 0 or 4

    const int ty = t >> 4;            // 0..15 -> row group
    const int tx = t & 15;            // 0..15 -> col group

    const float* Aptr = A + (size_t)(bm + lrow) * K + lcol;
    const float* Bptr = B + (size_t)(bn + lrow) * K + lcol;

    float acc[8][8];
#pragma unroll
    for (int i = 0; i < 8; i++)
#pragma unroll
        for (int j = 0; j < 8; j++) acc[i][j] = 0.f;

    for (int k0 = 0; k0 < K; k0 += BK) {
        float4 a = *(const float4*)(Aptr + k0);
        float4 b = *(const float4*)(Bptr + k0);
        As[lcol + 0][lrow] = a.x; As[lcol + 1][lrow] = a.y;
        As[lcol + 2][lrow] = a.z; As[lcol + 3][lrow] = a.w;
        Bs[lcol + 0][lrow] = b.x; Bs[lcol + 1][lrow] = b.y;
        Bs[lcol + 2][lrow] = b.z; Bs[lcol + 3][lrow] = b.w;
        __syncthreads();

#pragma unroll
        for (int k = 0; k < BK; k++) {
            float ar[8], br[8];
            *(float4*)&ar[0] = *(const float4*)&As[k][ty * 8];
            *(float4*)&ar[4] = *(const float4*)&As[k][ty * 8 + 4];
            *(float4*)&br[0] = *(const float4*)&Bs[k][tx * 8];
            *(float4*)&br[4] = *(const float4*)&Bs[k][tx * 8 + 4];
#pragma unroll
            for (int i = 0; i < 8; i++)
#pragma unroll
                for (int j = 0; j < 8; j++)
                    acc[i][j] += ar[i] * br[j];
        }
        __syncthreads();
    }

    // epilogue: + bias, float4 stores
#pragma unroll
    for (int i = 0; i < 8; i++) {
        const size_t row = (size_t)(bm + ty * 8 + i);
#pragma unroll
        for (int j = 0; j < 8; j += 4) {
            const int col = bn + tx * 8 + j;
            float4 r;
            r.x = acc[i][j + 0] + bias[col + 0];
            r.y = acc[i][j + 1] + bias[col + 1];
            r.z = acc[i][j + 2] + bias[col + 2];
            r.w = acc[i][j + 3] + bias[col + 3];
            *(float4*)&C[row * N + col] = r;
        }
    }
}

// ---------------------------------------------------------------------------
// Flash attention, fp32, causal + pad mask. One CTA = 128 query rows of one
// (b,h). Each thread owns one query row: q[64] and o[64] in registers.
// KV tiles of 16 rows staged through smem (float4). Online softmax.
// Reads g_qkv, writes g_ctx in [B,S,H,D] layout (ready for final GEMM).
// ---------------------------------------------------------------------------
#define BQ  128
#define BKV 16
#define NEG (-10000.0f)

__global__ void __launch_bounds__(128) flash_kernel(const int* __restrict__ amask)
{
    // reverse x order: heaviest (most KV tiles) blocks launch first
    const int qb = (int)(gridDim.x - 1 - blockIdx.x);
    const int h  = blockIdx.y;
    const int b  = blockIdx.z;
    const int t  = threadIdx.x;
    const int qrow = qb * BQ + t;

    __shared__ float4 Ks[BKV][HD / 4];
    __shared__ float4 Vs[BKV][HD / 4];
    __shared__ int    ms[BKV];

    const float scale = 0.125f;  // 64^-0.5

    // load + prescale q (scores = (q.k)*scale == (q*scale).k)
    float4 q[16];
    {
        const float* qptr = g_qkv + (size_t)(b * S_LEN + qrow) * (3 * EMB) + h * HD;
#pragma unroll
        for (int c = 0; c < 16; c++) {
            float4 v = ((const float4*)qptr)[c];
            v.x *= scale; v.y *= scale; v.z *= scale; v.w *= scale;
            q[c] = v;
        }
    }

    float4 o[16];
#pragma unroll
    for (int c = 0; c < 16; c++) o[c] = make_float4(0.f, 0.f, 0.f, 0.f);
    float m = -1e30f, l = 0.f;

    const int ntiles = (qb + 1) * (BQ / BKV);
    for (int jt = 0; jt < ntiles; jt++) {
        const int j0 = jt * BKV;
        __syncthreads();
        // cooperative tile load: 16 rows x 16 float4 = 256 float4, 2 per thread
#pragma unroll
        for (int u = 0; u < 2; u++) {
            const int idx = t + 128 * u;
            const int r = idx >> 4, c = idx & 15;
            const float* base = g_qkv + (size_t)(b * S_LEN + j0 + r) * (3 * EMB)
                                + h * HD + c * 4;
            Ks[r][c] = *(const float4*)(base + EMB);
            Vs[r][c] = *(const float4*)(base + 2 * EMB);
        }
        if (t < BKV) ms[t] = amask[b * S_LEN + j0 + t];
        __syncthreads();

        float p[BKV];
        float tmax = -1e30f;
#pragma unroll
        for (int j = 0; j < BKV; j++) {
            float4 a = make_float4(0.f, 0.f, 0.f, 0.f);
#pragma unroll
            for (int c = 0; c < 16; c++) {
                float4 kv = Ks[j][c];
                a.x += q[c].x * kv.x; a.y += q[c].y * kv.y;
                a.z += q[c].z * kv.z; a.w += q[c].w * kv.w;
            }
            float s = (a.x + a.y) + (a.z + a.w);
            const int jg = j0 + j;
            if (jg > qrow || ms[j] == 0) s = NEG;   // causal + pad mask
            p[j] = s;
            tmax = fmaxf(tmax, s);
        }

        const float mnew  = fmaxf(m, tmax);
        const float alpha = __expf(m - mnew);
        float lsum = 0.f;
#pragma unroll
        for (int j = 0; j < BKV; j++) {
            const float e = __expf(p[j] - mnew);
            p[j] = e;
            lsum += e;
        }
        l = l * alpha + lsum;
        m = mnew;

#pragma unroll
        for (int c = 0; c < 16; c++) {
            o[c].x *= alpha; o[c].y *= alpha; o[c].z *= alpha; o[c].w *= alpha;
        }
#pragma unroll
        for (int j = 0; j < BKV; j++) {
            const float pj = p[j];
#pragma unroll
            for (int c = 0; c < 16; c++) {
                float4 v = Vs[j][c];
                o[c].x += pj * v.x; o[c].y += pj * v.y;
                o[c].z += pj * v.z; o[c].w += pj * v.w;
            }
        }
    }

    const float inv = 1.f / l;
    float* optr = g_ctx + (size_t)(b * S_LEN + qrow) * EMB + h * HD;
#pragma unroll
    for (int c = 0; c < 16; c++) {
        float4 r = o[c];
        r.x *= inv; r.y *= inv; r.z *= inv; r.w *= inv;
        ((float4*)optr)[c] = r;
    }
}

// ---------------------------------------------------------------------------
// Launch: QKV GEMM -> flash attention -> output GEMM
// Inputs (metadata order): hidden_states, attention_mask, W_attn, b_attn,
//                          W_proj, b_proj
// ---------------------------------------------------------------------------
extern "C" void kernel_launch(void* const* d_in, const int* in_sizes, int n_in,
                              void* d_out, int out_size)
{
    const float* X     = (const float*)d_in[0];
    const int*   amask = (const int*)  d_in[1];
    const float* Wa    = (const float*)d_in[2];
    const float* ba    = (const float*)d_in[3];
    const float* Wp    = (const float*)d_in[4];
    const float* bp    = (const float*)d_in[5];
    float* out = (float*)d_out;

    // 1) qkv = X @ Wa^T + ba   -> g_qkv
    {
        dim3 grid(3 * EMB / 128, MTOT / 128);
        sgemm_nt_bias<<<grid, 256>>>(X, Wa, ba, nullptr, MTOT, 3 * EMB, EMB);
    }
    // 2) attention -> g_ctx
    {
        dim3 grid(S_LEN / BQ, NH, BATCH);
        flash_kernel<<<grid, 128>>>(amask);
    }
    // 3) out = ctx @ Wp^T + bp
    {
        dim3 grid(EMB / 128, MTOT / 128);
        sgemm_nt_bias<<<grid, 256>>>(nullptr, Wp, bp, out, MTOT, EMB, EMB);
    }
}

// round 5
// speedup vs baseline: 1.5168x; 1.5168x over previous
#include <cuda_runtime.h>
#include <cstdint>

#define S_LEN 2048
#define EMB   1024
#define NH    16
#define HD    64
#define BATCH 2
#define MTOT  (BATCH * S_LEN)   // 4096

// Scratch (allocation-free: __device__ globals)
__device__ float g_qkv[(size_t)MTOT * 3 * EMB];  // [4096, 3072] : q|k|v
__device__ float g_ctx[(size_t)MTOT * EMB];      // [4096, 1024] : [B,S,H,D]

// ============================ helpers ======================================
__device__ __forceinline__ uint32_t f2tf32(float v) {
    uint32_t r;
    asm("cvt.rna.tf32.f32 %0, %1;" : "=r"(r) : "f"(v));
    return r;
}
// D += A(16x8 row) * B(8x8 col), tf32 inputs, fp32 accum
__device__ __forceinline__ void mma_tf32(float& c0, float& c1, float& c2, float& c3,
                                         uint32_t a0, uint32_t a1, uint32_t a2, uint32_t a3,
                                         uint32_t b0, uint32_t b1) {
    asm volatile(
        "mma.sync.aligned.m16n8k8.row.col.f32.tf32.tf32.f32 "
        "{%0,%1,%2,%3}, {%4,%5,%6,%7}, {%8,%9}, {%0,%1,%2,%3};"
        : "+f"(c0), "+f"(c1), "+f"(c2), "+f"(c3)
        : "r"(a0), "r"(a1), "r"(a2), "r"(a3), "r"(b0), "r"(b1));
}

// ==================== tf32 mma.sync GEMM (NT) ==============================
// C[M,N] = A[M,K] @ B[N,K]^T + bias[N]
// CTA 128x128, BK=32, 256 threads (8 warps), warp tile 64x32 (grid 2x4).
#define GBM 128
#define GBN 128
#define GBK 32
#define STR 36   // padded smem row stride (floats): (4r+c)%32 conflict-free frags

__global__ void __launch_bounds__(256)
gemm_mma(const float* __restrict__ A_, const float* __restrict__ Bw,
         const float* __restrict__ bias, float* __restrict__ C_,
         int M, int N, int K)
{
    const float* A = A_ ? A_ : g_ctx;
    float* C = C_ ? C_ : g_qkv;

    __shared__ uint32_t As[GBM * STR];   // tf32 bits
    __shared__ uint32_t Bs[GBN * STR];

    const int t = threadIdx.x;
    const int warp = t >> 5, lane = t & 31;
    const int wr = warp >> 2, wc = warp & 3;       // warp grid 2 x 4
    const int gid = lane >> 2, tig = lane & 3;     // mma lane geometry
    const int bm = blockIdx.y * GBM, bn = blockIdx.x * GBN;

    // LDG mapping: idx = t + 256p -> row = idx/8, colseg = idx%8 (float4)
    const int lr = t >> 3, lc = (t & 7) * 4;

    float acc[4][4][4];
#pragma unroll
    for (int mt = 0; mt < 4; mt++)
#pragma unroll
        for (int nt = 0; nt < 4; nt++)
#pragma unroll
            for (int i = 0; i < 4; i++) acc[mt][nt][i] = 0.f;

    const int nCk = K / GBK;
    float4 ra[4], rb[4];

    // prologue: load + stage chunk 0
#pragma unroll
    for (int p = 0; p < 4; p++) {
        const int r = lr + 32 * p;
        ra[p] = *(const float4*)(A  + (size_t)(bm + r) * K + lc);
        rb[p] = *(const float4*)(Bw + (size_t)(bn + r) * K + lc);
    }
#pragma unroll
    for (int p = 0; p < 4; p++) {
        const int r = lr + 32 * p;
        uint32_t* pa = &As[r * STR + lc];
        uint32_t* pb = &Bs[r * STR + lc];
        pa[0] = f2tf32(ra[p].x); pa[1] = f2tf32(ra[p].y);
        pa[2] = f2tf32(ra[p].z); pa[3] = f2tf32(ra[p].w);
        pb[0] = f2tf32(rb[p].x); pb[1] = f2tf32(rb[p].y);
        pb[2] = f2tf32(rb[p].z); pb[3] = f2tf32(rb[p].w);
    }
    __syncthreads();

    for (int ck = 0; ck < nCk; ++ck) {
        const bool more = (ck + 1) < nCk;
        if (more) {
            const int koff = (ck + 1) * GBK;
#pragma unroll
            for (int p = 0; p < 4; p++) {
                const int r = lr + 32 * p;
                ra[p] = *(const float4*)(A  + (size_t)(bm + r) * K + koff + lc);
                rb[p] = *(const float4*)(Bw + (size_t)(bn + r) * K + koff + lc);
            }
        }
        // compute current chunk: 4 k-steps of 8
#pragma unroll
        for (int k0 = 0; k0 < GBK; k0 += 8) {
            uint32_t bf[4][2];
#pragma unroll
            for (int nt = 0; nt < 4; nt++) {
                const int n = wc * 32 + nt * 8 + gid;
                bf[nt][0] = Bs[n * STR + k0 + tig];
                bf[nt][1] = Bs[n * STR + k0 + tig + 4];
            }
#pragma unroll
            for (int mt = 0; mt < 4; mt++) {
                const int r = wr * 64 + mt * 16 + gid;
                const uint32_t a0 = As[r * STR + k0 + tig];
                const uint32_t a1 = As[(r + 8) * STR + k0 + tig];
                const uint32_t a2 = As[r * STR + k0 + tig + 4];
                const uint32_t a3 = As[(r + 8) * STR + k0 + tig + 4];
#pragma unroll
                for (int nt = 0; nt < 4; nt++)
                    mma_tf32(acc[mt][nt][0], acc[mt][nt][1],
                             acc[mt][nt][2], acc[mt][nt][3],
                             a0, a1, a2, a3, bf[nt][0], bf[nt][1]);
            }
        }
        if (more) {
            __syncthreads();   // everyone done reading smem
#pragma unroll
            for (int p = 0; p < 4; p++) {
                const int r = lr + 32 * p;
                uint32_t* pa = &As[r * STR + lc];
                uint32_t* pb = &Bs[r * STR + lc];
                pa[0] = f2tf32(ra[p].x); pa[1] = f2tf32(ra[p].y);
                pa[2] = f2tf32(ra[p].z); pa[3] = f2tf32(ra[p].w);
                pb[0] = f2tf32(rb[p].x); pb[1] = f2tf32(rb[p].y);
                pb[2] = f2tf32(rb[p].z); pb[3] = f2tf32(rb[p].w);
            }
            __syncthreads();
        }
    }

    // epilogue: C = acc + bias (float2 stores; c0,c1 are adjacent columns)
#pragma unroll
    for (int mt = 0; mt < 4; mt++) {
        const int row0 = bm + wr * 64 + mt * 16 + gid;
#pragma unroll
        for (int nt = 0; nt < 4; nt++) {
            const int col = bn + wc * 32 + nt * 8 + tig * 2;
            const float b0 = bias[col], b1 = bias[col + 1];
            float2 v0 = make_float2(acc[mt][nt][0] + b0, acc[mt][nt][1] + b1);
            float2 v1 = make_float2(acc[mt][nt][2] + b0, acc[mt][nt][3] + b1);
            *(float2*)&C[(size_t)row0 * N + col] = v0;
            *(float2*)&C[(size_t)(row0 + 8) * N + col] = v1;
        }
    }
}

// ======================== Flash attention (fp32) ===========================
#define BQ  128
#define BKV 16
#define NEG (-10000.0f)

__global__ void __launch_bounds__(128) flash_kernel(const int* __restrict__ amask)
{
    const int qb = (int)(gridDim.x - 1 - blockIdx.x);  // heavy blocks first
    const int h  = blockIdx.y;
    const int b  = blockIdx.z;
    const int t  = threadIdx.x;
    const int qrow = qb * BQ + t;

    __shared__ float4 Ks[BKV][HD / 4];
    __shared__ float4 Vs[BKV][HD / 4];
    __shared__ int    ms[BKV];

    const float scale = 0.125f;  // 64^-0.5

    float4 q[16];
    {
        const float* qptr = g_qkv + (size_t)(b * S_LEN + qrow) * (3 * EMB) + h * HD;
#pragma unroll
        for (int c = 0; c < 16; c++) {
            float4 v = ((const float4*)qptr)[c];
            v.x *= scale; v.y *= scale; v.z *= scale; v.w *= scale;
            q[c] = v;
        }
    }

    float4 o[16];
#pragma unroll
    for (int c = 0; c < 16; c++) o[c] = make_float4(0.f, 0.f, 0.f, 0.f);
    float m = -1e30f, l = 0.f;

    const int ntiles = (qb + 1) * (BQ / BKV);
    for (int jt = 0; jt < ntiles; jt++) {
        const int j0 = jt * BKV;
        __syncthreads();
#pragma unroll
        for (int u = 0; u < 2; u++) {
            const int idx = t + 128 * u;
            const int r = idx >> 4, c = idx & 15;
            const float* base = g_qkv + (size_t)(b * S_LEN + j0 + r) * (3 * EMB)
                                + h * HD + c * 4;
            Ks[r][c] = *(const float4*)(base + EMB);
            Vs[r][c] = *(const float4*)(base + 2 * EMB);
        }
        if (t < BKV) ms[t] = amask[b * S_LEN + j0 + t];
        __syncthreads();

        float p[BKV];
        float tmax = -1e30f;
#pragma unroll
        for (int j = 0; j < BKV; j++) {
            float4 a = make_float4(0.f, 0.f, 0.f, 0.f);
#pragma unroll
            for (int c = 0; c < 16; c++) {
                float4 kv = Ks[j][c];
                a.x += q[c].x * kv.x; a.y += q[c].y * kv.y;
                a.z += q[c].z * kv.z; a.w += q[c].w * kv.w;
            }
            float s = (a.x + a.y) + (a.z + a.w);
            const int jg = j0 + j;
            if (jg > qrow || ms[j] == 0) s = NEG;
            p[j] = s;
            tmax = fmaxf(tmax, s);
        }

        const float mnew  = fmaxf(m, tmax);
        const float alpha = __expf(m - mnew);
        float lsum = 0.f;
#pragma unroll
        for (int j = 0; j < BKV; j++) {
            const float e = __expf(p[j] - mnew);
            p[j] = e;
            lsum += e;
        }
        l = l * alpha + lsum;
        m = mnew;

#pragma unroll
        for (int c = 0; c < 16; c++) {
            o[c].x *= alpha; o[c].y *= alpha; o[c].z *= alpha; o[c].w *= alpha;
        }
#pragma unroll
        for (int j = 0; j < BKV; j++) {
            const float pj = p[j];
#pragma unroll
            for (int c = 0; c < 16; c++) {
                float4 v = Vs[j][c];
                o[c].x += pj * v.x; o[c].y += pj * v.y;
                o[c].z += pj * v.z; o[c].w += pj * v.w;
            }
        }
    }

    const float inv = 1.f / l;
    float* optr = g_ctx + (size_t)(b * S_LEN + qrow) * EMB + h * HD;
#pragma unroll
    for (int c = 0; c < 16; c++) {
        float4 r = o[c];
        r.x *= inv; r.y *= inv; r.z *= inv; r.w *= inv;
        ((float4*)optr)[c] = r;
    }
}

// =============================== Launch ====================================
extern "C" void kernel_launch(void* const* d_in, const int* in_sizes, int n_in,
                              void* d_out, int out_size)
{
    const float* X     = (const float*)d_in[0];
    const int*   amask = (const int*)  d_in[1];
    const float* Wa    = (const float*)d_in[2];
    const float* ba    = (const float*)d_in[3];
    const float* Wp    = (const float*)d_in[4];
    const float* bp    = (const float*)d_in[5];
    float* out = (float*)d_out;

    // 1) qkv = X @ Wa^T + ba   -> g_qkv
    {
        dim3 grid(3 * EMB / GBN, MTOT / GBM);
        gemm_mma<<<grid, 256>>>(X, Wa, ba, nullptr, MTOT, 3 * EMB, EMB);
    }
    // 2) attention -> g_ctx
    {
        dim3 grid(S_LEN / BQ, NH, BATCH);
        flash_kernel<<<grid, 128>>>(amask);
    }
    // 3) out = ctx @ Wp^T + bp
    {
        dim3 grid(EMB / GBN, MTOT / GBM);
        gemm_mma<<<grid, 256>>>(nullptr, Wp, bp, out, MTOT, EMB, EMB);
    }
}

// round 6
// speedup vs baseline: 3.4840x; 2.2969x over previous
#include <cuda_runtime.h>
#include <cstdint>

#define S_LEN 2048
#define EMB   1024
#define NH    16
#define HD    64
#define BATCH 2
#define MTOT  (BATCH * S_LEN)   // 4096
#define NEG   (-10000.0f)

// Scratch (allocation-free: __device__ globals)
__device__ float g_qkv[(size_t)MTOT * 3 * EMB];  // [4096, 3072] : q|k|v
__device__ float g_ctx[(size_t)MTOT * EMB];      // [4096, 1024] : [B,S,H,D]

// ============================ helpers ======================================
__device__ __forceinline__ uint32_t smem_u32(const void* p) {
    uint32_t a;
    asm("{ .reg .u64 t; cvta.to.shared.u64 t, %1; cvt.u32.u64 %0, t; }"
        : "=r"(a) : "l"(p));
    return a;
}
__device__ __forceinline__ uint32_t f2tf32(float v) {
    uint32_t r;
    asm("cvt.rna.tf32.f32 %0, %1;" : "=r"(r) : "f"(v));
    return r;
}
// pack two fp32 -> f16x2, lo in low half
__device__ __forceinline__ uint32_t packh2(float lo, float hi) {
    uint32_t r;
    asm("cvt.rn.f16x2.f32 %0, %1, %2;" : "=r"(r) : "f"(hi), "f"(lo));
    return r;
}
__device__ __forceinline__ void mma_tf32(float& c0, float& c1, float& c2, float& c3,
                                         uint32_t a0, uint32_t a1, uint32_t a2, uint32_t a3,
                                         uint32_t b0, uint32_t b1) {
    asm volatile(
        "mma.sync.aligned.m16n8k8.row.col.f32.tf32.tf32.f32 "
        "{%0,%1,%2,%3}, {%4,%5,%6,%7}, {%8,%9}, {%0,%1,%2,%3};"
        : "+f"(c0), "+f"(c1), "+f"(c2), "+f"(c3)
        : "r"(a0), "r"(a1), "r"(a2), "r"(a3), "r"(b0), "r"(b1));
}
__device__ __forceinline__ void mma_f16(float& c0, float& c1, float& c2, float& c3,
                                        uint32_t a0, uint32_t a1, uint32_t a2, uint32_t a3,
                                        uint32_t b0, uint32_t b1) {
    asm volatile(
        "mma.sync.aligned.m16n8k16.row.col.f32.f16.f16.f32 "
        "{%0,%1,%2,%3}, {%4,%5,%6,%7}, {%8,%9}, {%0,%1,%2,%3};"
        : "+f"(c0), "+f"(c1), "+f"(c2), "+f"(c3)
        : "r"(a0), "r"(a1), "r"(a2), "r"(a3), "r"(b0), "r"(b1));
}
__device__ __forceinline__ void cp_async16(uint32_t dst, const void* src) {
    asm volatile("cp.async.cg.shared.global [%0], [%1], 16;" :: "r"(dst), "l"(src));
}
__device__ __forceinline__ void cp_commit() {
    asm volatile("cp.async.commit_group;" ::: "memory");
}
__device__ __forceinline__ void cp_wait1() {
    asm volatile("cp.async.wait_group 1;" ::: "memory");
}
__device__ __forceinline__ void cp_wait0() {
    asm volatile("cp.async.wait_group 0;" ::: "memory");
}

// ==================== tf32 mma.sync GEMM (NT) ==============================
// C[M,N] = A[M,K] @ B[N,K]^T + bias[N]  (verified R5 kernel, unchanged)
#define GBM 128
#define GBN 128
#define GBK 32
#define STR 36

__global__ void __launch_bounds__(256)
gemm_mma(const float* __restrict__ A_, const float* __restrict__ Bw,
         const float* __restrict__ bias, float* __restrict__ C_,
         int M, int N, int K)
{
    const float* A = A_ ? A_ : g_ctx;
    float* C = C_ ? C_ : g_qkv;

    __shared__ uint32_t As[GBM * STR];
    __shared__ uint32_t Bs[GBN * STR];

    const int t = threadIdx.x;
    const int warp = t >> 5, lane = t & 31;
    const int wr = warp >> 2, wc = warp & 3;
    const int gid = lane >> 2, tig = lane & 3;
    const int bm = blockIdx.y * GBM, bn = blockIdx.x * GBN;
    const int lr = t >> 3, lc = (t & 7) * 4;

    float acc[4][4][4];
#pragma unroll
    for (int mt = 0; mt < 4; mt++)
#pragma unroll
        for (int nt = 0; nt < 4; nt++)
#pragma unroll
            for (int i = 0; i < 4; i++) acc[mt][nt][i] = 0.f;

    const int nCk = K / GBK;
    float4 ra[4], rb[4];

#pragma unroll
    for (int p = 0; p < 4; p++) {
        const int r = lr + 32 * p;
        ra[p] = *(const float4*)(A  + (size_t)(bm + r) * K + lc);
        rb[p] = *(const float4*)(Bw + (size_t)(bn + r) * K + lc);
    }
#pragma unroll
    for (int p = 0; p < 4; p++) {
        const int r = lr + 32 * p;
        uint32_t* pa = &As[r * STR + lc];
        uint32_t* pb = &Bs[r * STR + lc];
        pa[0] = f2tf32(ra[p].x); pa[1] = f2tf32(ra[p].y);
        pa[2] = f2tf32(ra[p].z); pa[3] = f2tf32(ra[p].w);
        pb[0] = f2tf32(rb[p].x); pb[1] = f2tf32(rb[p].y);
        pb[2] = f2tf32(rb[p].z); pb[3] = f2tf32(rb[p].w);
    }
    __syncthreads();

    for (int ck = 0; ck < nCk; ++ck) {
        const bool more = (ck + 1) < nCk;
        if (more) {
            const int koff = (ck + 1) * GBK;
#pragma unroll
            for (int p = 0; p < 4; p++) {
                const int r = lr + 32 * p;
                ra[p] = *(const float4*)(A  + (size_t)(bm + r) * K + koff + lc);
                rb[p] = *(const float4*)(Bw + (size_t)(bn + r) * K + koff + lc);
            }
        }
#pragma unroll
        for (int k0 = 0; k0 < GBK; k0 += 8) {
            uint32_t bf[4][2];
#pragma unroll
            for (int nt = 0; nt < 4; nt++) {
                const int n = wc * 32 + nt * 8 + gid;
                bf[nt][0] = Bs[n * STR + k0 + tig];
                bf[nt][1] = Bs[n * STR + k0 + tig + 4];
            }
#pragma unroll
            for (int mt = 0; mt < 4; mt++) {
                const int r = wr * 64 + mt * 16 + gid;
                const uint32_t a0 = As[r * STR + k0 + tig];
                const uint32_t a1 = As[(r + 8) * STR + k0 + tig];
                const uint32_t a2 = As[r * STR + k0 + tig + 4];
                const uint32_t a3 = As[(r + 8) * STR + k0 + tig + 4];
#pragma unroll
                for (int nt = 0; nt < 4; nt++)
                    mma_tf32(acc[mt][nt][0], acc[mt][nt][1],
                             acc[mt][nt][2], acc[mt][nt][3],
                             a0, a1, a2, a3, bf[nt][0], bf[nt][1]);
            }
        }
        if (more) {
            __syncthreads();
#pragma unroll
            for (int p = 0; p < 4; p++) {
                const int r = lr + 32 * p;
                uint32_t* pa = &As[r * STR + lc];
                uint32_t* pb = &Bs[r * STR + lc];
                pa[0] = f2tf32(ra[p].x); pa[1] = f2tf32(ra[p].y);
                pa[2] = f2tf32(ra[p].z); pa[3] = f2tf32(ra[p].w);
                pb[0] = f2tf32(rb[p].x); pb[1] = f2tf32(rb[p].y);
                pb[2] = f2tf32(rb[p].z); pb[3] = f2tf32(rb[p].w);
            }
            __syncthreads();
        }
    }

#pragma unroll
    for (int mt = 0; mt < 4; mt++) {
        const int row0 = bm + wr * 64 + mt * 16 + gid;
#pragma unroll
        for (int nt = 0; nt < 4; nt++) {
            const int col = bn + wc * 32 + nt * 8 + tig * 2;
            const float b0 = bias[col], b1 = bias[col + 1];
            float2 v0 = make_float2(acc[mt][nt][0] + b0, acc[mt][nt][1] + b1);
            float2 v1 = make_float2(acc[mt][nt][2] + b0, acc[mt][nt][3] + b1);
            *(float2*)&C[(size_t)row0 * N + col] = v0;
            *(float2*)&C[(size_t)(row0 + 8) * N + col] = v1;
        }
    }
}

// ================= Tensor-core flash attention =============================
// CTA = 64 q rows of one (b,h), 4 warps (16 q rows each), BKV = 64.
// QK^T: tf32 m16n8k8 (Q frags in regs, K fp32-as-tf32 from smem).
// P*V : fp16 m16n8k16 (P in regs from S accum layout, V fp32->f16x2 from smem).
// K/V double-buffered via cp.async.
#define FSTR 68                       // smem row stride (floats): conflict-free frags
#define FTILE (64 * FSTR)             // 4352 floats per K or V tile
// layout (floats): K0 | V0 | K1 | V1 | msb[2][64]
#define FLASH_SMEM ((4 * FTILE + 128) * 4)

__global__ void __launch_bounds__(128)
flash_tc(const int* __restrict__ amask)
{
    extern __shared__ float fsm[];
    const int qb = 31 - (int)blockIdx.x;      // heavy (many-tile) blocks first
    const int h  = blockIdx.y;
    const int b  = blockIdx.z;
    const int t  = threadIdx.x;
    const int wid = t >> 5, lane = t & 31;
    const int g = lane >> 2, tg = lane & 3;

    float* const kbuf[2] = { fsm,             fsm + 2 * FTILE };
    float* const vbuf[2] = { fsm + FTILE,     fsm + 3 * FTILE };
    float* const msb     = fsm + 4 * FTILE;   // [2][64]

    // ---- Q fragments (tf32, pre-scaled) ----
    const int qrlo = qb * 64 + wid * 16 + g;  // this thread's low q row
    const float* qlo = g_qkv + ((size_t)(b * S_LEN) + qrlo) * 3072 + h * 64;
    const float* qhi = qlo + (size_t)8 * 3072;
    uint32_t qf[8][4];
#pragma unroll
    for (int kk = 0; kk < 8; kk++) {
        qf[kk][0] = f2tf32(qlo[8 * kk + tg] * 0.125f);
        qf[kk][1] = f2tf32(qhi[8 * kk + tg] * 0.125f);
        qf[kk][2] = f2tf32(qlo[8 * kk + tg + 4] * 0.125f);
        qf[kk][3] = f2tf32(qhi[8 * kk + tg + 4] * 0.125f);
    }

    float oa[8][4];
#pragma unroll
    for (int j = 0; j < 8; j++)
#pragma unroll
        for (int i = 0; i < 4; i++) oa[j][i] = 0.f;
    float m0 = -1e30f, m1 = -1e30f, l0 = 0.f, l1 = 0.f;

    // tile issue: K,V 64x64 floats each via cp.async + pad-bias into msb
    auto issue = [&](int jt) {
        const int buf = jt & 1;
        float* ks = kbuf[buf];
        float* vs = vbuf[buf];
        const int j0 = jt * 64;
#pragma unroll
        for (int u = 0; u < 8; u++) {
            const int idx = t + 128 * u;
            const int r = idx >> 4, c4 = (idx & 15) * 4;
            const float* src = g_qkv + ((size_t)(b * S_LEN) + j0 + r) * 3072
                               + 1024 + h * 64 + c4;
            cp_async16(smem_u32(ks + r * FSTR + c4), src);
            cp_async16(smem_u32(vs + r * FSTR + c4), src + 1024);
        }
        if (t < 64)
            msb[buf * 64 + t] = amask[b * S_LEN + j0 + t] ? 0.f : NEG;
        cp_commit();
    };

    issue(0);

    for (int jt = 0; jt <= qb; jt++) {
        if (jt < qb) { issue(jt + 1); cp_wait1(); }
        else         { cp_wait0(); }
        __syncthreads();

        const int buf = jt & 1;
        const float*    vs = vbuf[buf];
        const uint32_t* ks = (const uint32_t*)kbuf[buf];
        const float*    mb = msb + buf * 64;

        // ---- S = Q K^T (tf32) ----
        float sc[8][4];
#pragma unroll
        for (int j = 0; j < 8; j++)
#pragma unroll
            for (int i = 0; i < 4; i++) sc[j][i] = 0.f;
#pragma unroll
        for (int kk = 0; kk < 8; kk++) {
#pragma unroll
            for (int j = 0; j < 8; j++) {
                const uint32_t* kr = ks + (8 * j + g) * FSTR + 8 * kk + tg;
                mma_tf32(sc[j][0], sc[j][1], sc[j][2], sc[j][3],
                         qf[kk][0], qf[kk][1], qf[kk][2], qf[kk][3],
                         kr[0], kr[4]);
            }
        }

        // ---- masks + online softmax ----
        const bool diag = (jt == qb);
        const int rlo = wid * 16 + g, rhi = rlo + 8;
        float tm0 = -1e30f, tm1 = -1e30f;
#pragma unroll
        for (int j = 0; j < 8; j++) {
            const float2 mm = *(const float2*)&mb[8 * j + 2 * tg];
            float c0 = sc[j][0] + mm.x, c1 = sc[j][1] + mm.y;
            float c2 = sc[j][2] + mm.x, c3 = sc[j][3] + mm.y;
            if (diag) {
                const int kv = 8 * j + 2 * tg;
                c0 = (kv     > rlo) ? NEG : c0;
                c1 = (kv + 1 > rlo) ? NEG : c1;
                c2 = (kv     > rhi) ? NEG : c2;
                c3 = (kv + 1 > rhi) ? NEG : c3;
            }
            sc[j][0] = c0; sc[j][1] = c1; sc[j][2] = c2; sc[j][3] = c3;
            tm0 = fmaxf(tm0, fmaxf(c0, c1));
            tm1 = fmaxf(tm1, fmaxf(c2, c3));
        }
        tm0 = fmaxf(tm0, __shfl_xor_sync(0xffffffffu, tm0, 1));
        tm0 = fmaxf(tm0, __shfl_xor_sync(0xffffffffu, tm0, 2));
        tm1 = fmaxf(tm1, __shfl_xor_sync(0xffffffffu, tm1, 1));
        tm1 = fmaxf(tm1, __shfl_xor_sync(0xffffffffu, tm1, 2));

        const float mn0 = fmaxf(m0, tm0), mn1 = fmaxf(m1, tm1);
        const float al0 = __expf(m0 - mn0), al1 = __expf(m1 - mn1);
        float s0 = 0.f, s1 = 0.f;
#pragma unroll
        for (int j = 0; j < 8; j++) {
            sc[j][0] = __expf(sc[j][0] - mn0);
            sc[j][1] = __expf(sc[j][1] - mn0);
            sc[j][2] = __expf(sc[j][2] - mn1);
            sc[j][3] = __expf(sc[j][3] - mn1);
            s0 += sc[j][0] + sc[j][1];
            s1 += sc[j][2] + sc[j][3];
        }
        s0 += __shfl_xor_sync(0xffffffffu, s0, 1);
        s0 += __shfl_xor_sync(0xffffffffu, s0, 2);
        s1 += __shfl_xor_sync(0xffffffffu, s1, 1);
        s1 += __shfl_xor_sync(0xffffffffu, s1, 2);
        l0 = l0 * al0 + s0; l1 = l1 * al1 + s1;
        m0 = mn0; m1 = mn1;
#pragma unroll
        for (int j = 0; j < 8; j++) {
            oa[j][0] *= al0; oa[j][1] *= al0;
            oa[j][2] *= al1; oa[j][3] *= al1;
        }

        // ---- O += P V (fp16) ----
#pragma unroll
        for (int kk = 0; kk < 4; kk++) {
            const uint32_t a0 = packh2(sc[2 * kk][0],     sc[2 * kk][1]);
            const uint32_t a1 = packh2(sc[2 * kk][2],     sc[2 * kk][3]);
            const uint32_t a2 = packh2(sc[2 * kk + 1][0], sc[2 * kk + 1][1]);
            const uint32_t a3 = packh2(sc[2 * kk + 1][2], sc[2 * kk + 1][3]);
            const float* vk = vs + (16 * kk + 2 * tg) * FSTR + g;
#pragma unroll
            for (int j2 = 0; j2 < 8; j2++) {
                const float* vc = vk + 8 * j2;
                const uint32_t b0 = packh2(vc[0],        vc[FSTR]);
                const uint32_t b1 = packh2(vc[8 * FSTR], vc[9 * FSTR]);
                mma_f16(oa[j2][0], oa[j2][1], oa[j2][2], oa[j2][3],
                        a0, a1, a2, a3, b0, b1);
            }
        }
        __syncthreads();
    }

    // ---- epilogue: O /= l -> g_ctx[b, q, h, d] ----
    const float i0 = 1.f / l0, i1 = 1.f / l1;
    float* olo = g_ctx + ((size_t)(b * S_LEN) + qrlo) * EMB + h * 64;
    float* ohi = olo + (size_t)8 * EMB;
#pragma unroll
    for (int j2 = 0; j2 < 8; j2++) {
        const int d = 8 * j2 + 2 * tg;
        *(float2*)&olo[d] = make_float2(oa[j2][0] * i0, oa[j2][1] * i0);
        *(float2*)&ohi[d] = make_float2(oa[j2][2] * i1, oa[j2][3] * i1);
    }
}

// =============================== Launch ====================================
extern "C" void kernel_launch(void* const* d_in, const int* in_sizes, int n_in,
                              void* d_out, int out_size)
{
    const float* X     = (const float*)d_in[0];
    const int*   amask = (const int*)  d_in[1];
    const float* Wa    = (const float*)d_in[2];
    const float* ba    = (const float*)d_in[3];
    const float* Wp    = (const float*)d_in[4];
    const float* bp    = (const float*)d_in[5];
    float* out = (float*)d_out;

    cudaFuncSetAttribute(flash_tc, cudaFuncAttributeMaxDynamicSharedMemorySize,
                         FLASH_SMEM);

    // 1) qkv = X @ Wa^T + ba   -> g_qkv
    {
        dim3 grid(3 * EMB / GBN, MTOT / GBM);
        gemm_mma<<<grid, 256>>>(X, Wa, ba, nullptr, MTOT, 3 * EMB, EMB);
    }
    // 2) attention -> g_ctx
    {
        dim3 grid(S_LEN / 64, NH, BATCH);
        flash_tc<<<grid, 128, FLASH_SMEM>>>(amask);
    }
    // 3) out = ctx @ Wp^T + bp
    {
        dim3 grid(EMB / GBN, MTOT / GBM);
        gemm_mma<<<grid, 256>>>(nullptr, Wp, bp, out, MTOT, EMB, EMB);
    }
}

// round 7
// speedup vs baseline: 4.0796x; 1.1710x over previous
#include <cuda_runtime.h>
#include <cstdint>

#define S_LEN 2048
#define EMB   1024
#define NH    16
#define HD    64
#define BATCH 2
#define MTOT  (BATCH * S_LEN)   // 4096
#define NEG   (-10000.0f)

// Scratch (allocation-free: __device__ globals)
__device__ float g_qkv[(size_t)MTOT * 3 * EMB];  // [4096, 3072] : q|k|v
__device__ float g_ctx[(size_t)MTOT * EMB];      // [4096, 1024] : [B,S,H,D]

// ============================ helpers ======================================
__device__ __forceinline__ uint32_t smem_u32(const void* p) {
    uint32_t a;
    asm("{ .reg .u64 t; cvta.to.shared.u64 t, %1; cvt.u32.u64 %0, t; }"
        : "=r"(a) : "l"(p));
    return a;
}
__device__ __forceinline__ uint32_t f2tf32(float v) {
    uint32_t r;
    asm("cvt.rna.tf32.f32 %0, %1;" : "=r"(r) : "f"(v));
    return r;
}
// pack two fp32 -> f16x2, lo in low half
__device__ __forceinline__ uint32_t packh2(float lo, float hi) {
    uint32_t r;
    asm("cvt.rn.f16x2.f32 %0, %1, %2;" : "=r"(r) : "f"(hi), "f"(lo));
    return r;
}
__device__ __forceinline__ void mma_tf32(float& c0, float& c1, float& c2, float& c3,
                                         uint32_t a0, uint32_t a1, uint32_t a2, uint32_t a3,
                                         uint32_t b0, uint32_t b1) {
    asm volatile(
        "mma.sync.aligned.m16n8k8.row.col.f32.tf32.tf32.f32 "
        "{%0,%1,%2,%3}, {%4,%5,%6,%7}, {%8,%9}, {%0,%1,%2,%3};"
        : "+f"(c0), "+f"(c1), "+f"(c2), "+f"(c3)
        : "r"(a0), "r"(a1), "r"(a2), "r"(a3), "r"(b0), "r"(b1));
}
__device__ __forceinline__ void mma_f16(float& c0, float& c1, float& c2, float& c3,
                                        uint32_t a0, uint32_t a1, uint32_t a2, uint32_t a3,
                                        uint32_t b0, uint32_t b1) {
    asm volatile(
        "mma.sync.aligned.m16n8k16.row.col.f32.f16.f16.f32 "
        "{%0,%1,%2,%3}, {%4,%5,%6,%7}, {%8,%9}, {%0,%1,%2,%3};"
        : "+f"(c0), "+f"(c1), "+f"(c2), "+f"(c3)
        : "r"(a0), "r"(a1), "r"(a2), "r"(a3), "r"(b0), "r"(b1));
}
__device__ __forceinline__ void cp_async16(uint32_t dst, const void* src) {
    asm volatile("cp.async.cg.shared.global [%0], [%1], 16;" :: "r"(dst), "l"(src));
}
__device__ __forceinline__ void cp_commit() {
    asm volatile("cp.async.commit_group;" ::: "memory");
}
__device__ __forceinline__ void cp_wait1() {
    asm volatile("cp.async.wait_group 1;" ::: "memory");
}
__device__ __forceinline__ void cp_wait0() {
    asm volatile("cp.async.wait_group 0;" ::: "memory");
}
// half-ulp rounding for fp32-bits -> tf32 truncation inside mma
#define RND 0x1000u

// ==================== tf32 mma.sync GEMM (NT), cp.async pipelined ==========
// C[M,N] = A[M,K] @ B[N,K]^T + bias[N]
// CTA 128x128, BK=32, 256 threads, warp tile 64x32, 2-stage cp.async.
#define GBM 128
#define GBN 128
#define GBK 32
#define STR 36                       // padded row stride (16B-aligned: 144B)
#define TSZ (GBM * STR)              // floats per operand tile per stage
#define GEMM_SMEM (2 * 2 * TSZ * 4)  // 2 stages x (A+B) = 72 KB

__global__ void __launch_bounds__(256, 2)
gemm_mma(const float* __restrict__ A_, const float* __restrict__ Bw,
         const float* __restrict__ bias, float* __restrict__ C_,
         int M, int N, int K)
{
    const float* A = A_ ? A_ : g_ctx;
    float* C = C_ ? C_ : g_qkv;

    extern __shared__ uint32_t gsm[];
    uint32_t* const As = gsm;             // [2][TSZ]
    uint32_t* const Bs = gsm + 2 * TSZ;   // [2][TSZ]

    const int t = threadIdx.x;
    const int warp = t >> 5, lane = t & 31;
    const int wr = warp >> 2, wc = warp & 3;     // warp grid 2x4
    const int gid = lane >> 2, tig = lane & 3;
    const int bm = blockIdx.y * GBM, bn = blockIdx.x * GBN;
    const int lr = t >> 3, lc = (t & 7) * 4;     // cp.async mapping

    float acc[4][4][4];
#pragma unroll
    for (int mt = 0; mt < 4; mt++)
#pragma unroll
        for (int nt = 0; nt < 4; nt++)
#pragma unroll
            for (int i = 0; i < 4; i++) acc[mt][nt][i] = 0.f;

    const int nCk = K / GBK;

    // raw fp32 bytes -> smem; tf32 rounding handled at frag load (+RND)
    auto issue = [&](int ck) {
        const int s = ck & 1;
        const int koff = ck * GBK;
#pragma unroll
        for (int u = 0; u < 4; u++) {
            const int r = lr + 32 * u;
            cp_async16(smem_u32(&As[s * TSZ + r * STR + lc]),
                       A + (size_t)(bm + r) * K + koff + lc);
            cp_async16(smem_u32(&Bs[s * TSZ + r * STR + lc]),
                       Bw + (size_t)(bn + r) * K + koff + lc);
        }
        cp_commit();
    };

    issue(0);

    for (int ck = 0; ck < nCk; ++ck) {
        const bool more = (ck + 1) < nCk;
        if (more) { issue(ck + 1); cp_wait1(); }
        else      { cp_wait0(); }
        __syncthreads();

        const uint32_t* as = As + (ck & 1) * TSZ;
        const uint32_t* bs = Bs + (ck & 1) * TSZ;
#pragma unroll
        for (int k0 = 0; k0 < GBK; k0 += 8) {
            uint32_t bf[4][2];
#pragma unroll
            for (int nt = 0; nt < 4; nt++) {
                const int n = wc * 32 + nt * 8 + gid;
                bf[nt][0] = bs[n * STR + k0 + tig] + RND;
                bf[nt][1] = bs[n * STR + k0 + tig + 4] + RND;
            }
#pragma unroll
            for (int mt = 0; mt < 4; mt++) {
                const int r = wr * 64 + mt * 16 + gid;
                const uint32_t a0 = as[r * STR + k0 + tig] + RND;
                const uint32_t a1 = as[(r + 8) * STR + k0 + tig] + RND;
                const uint32_t a2 = as[r * STR + k0 + tig + 4] + RND;
                const uint32_t a3 = as[(r + 8) * STR + k0 + tig + 4] + RND;
#pragma unroll
                for (int nt = 0; nt < 4; nt++)
                    mma_tf32(acc[mt][nt][0], acc[mt][nt][1],
                             acc[mt][nt][2], acc[mt][nt][3],
                             a0, a1, a2, a3, bf[nt][0], bf[nt][1]);
            }
        }
        __syncthreads();   // stage (ck&1) free for issue(ck+2)
    }

    // epilogue: C = acc + bias
#pragma unroll
    for (int mt = 0; mt < 4; mt++) {
        const int row0 = bm + wr * 64 + mt * 16 + gid;
#pragma unroll
        for (int nt = 0; nt < 4; nt++) {
            const int col = bn + wc * 32 + nt * 8 + tig * 2;
            const float b0 = bias[col], b1 = bias[col + 1];
            float2 v0 = make_float2(acc[mt][nt][0] + b0, acc[mt][nt][1] + b1);
            float2 v1 = make_float2(acc[mt][nt][2] + b0, acc[mt][nt][3] + b1);
            *(float2*)&C[(size_t)row0 * N + col] = v0;
            *(float2*)&C[(size_t)(row0 + 8) * N + col] = v1;
        }
    }
}

// ================= Tensor-core flash attention (R6, unchanged) =============
#define FSTR 68
#define FTILE (64 * FSTR)
#define FLASH_SMEM ((4 * FTILE + 128) * 4)

__global__ void __launch_bounds__(128)
flash_tc(const int* __restrict__ amask)
{
    extern __shared__ float fsm[];
    const int qb = 31 - (int)blockIdx.x;
    const int h  = blockIdx.y;
    const int b  = blockIdx.z;
    const int t  = threadIdx.x;
    const int wid = t >> 5, lane = t & 31;
    const int g = lane >> 2, tg = lane & 3;

    float* const kbuf[2] = { fsm,             fsm + 2 * FTILE };
    float* const vbuf[2] = { fsm + FTILE,     fsm + 3 * FTILE };
    float* const msb     = fsm + 4 * FTILE;

    const int qrlo = qb * 64 + wid * 16 + g;
    const float* qlo = g_qkv + ((size_t)(b * S_LEN) + qrlo) * 3072 + h * 64;
    const float* qhi = qlo + (size_t)8 * 3072;
    uint32_t qf[8][4];
#pragma unroll
    for (int kk = 0; kk < 8; kk++) {
        qf[kk][0] = f2tf32(qlo[8 * kk + tg] * 0.125f);
        qf[kk][1] = f2tf32(qhi[8 * kk + tg] * 0.125f);
        qf[kk][2] = f2tf32(qlo[8 * kk + tg + 4] * 0.125f);
        qf[kk][3] = f2tf32(qhi[8 * kk + tg + 4] * 0.125f);
    }

    float oa[8][4];
#pragma unroll
    for (int j = 0; j < 8; j++)
#pragma unroll
        for (int i = 0; i < 4; i++) oa[j][i] = 0.f;
    float m0 = -1e30f, m1 = -1e30f, l0 = 0.f, l1 = 0.f;

    auto issue = [&](int jt) {
        const int buf = jt & 1;
        float* ks = kbuf[buf];
        float* vs = vbuf[buf];
        const int j0 = jt * 64;
#pragma unroll
        for (int u = 0; u < 8; u++) {
            const int idx = t + 128 * u;
            const int r = idx >> 4, c4 = (idx & 15) * 4;
            const float* src = g_qkv + ((size_t)(b * S_LEN) + j0 + r) * 3072
                               + 1024 + h * 64 + c4;
            cp_async16(smem_u32(ks + r * FSTR + c4), src);
            cp_async16(smem_u32(vs + r * FSTR + c4), src + 1024);
        }
        if (t < 64)
            msb[buf * 64 + t] = amask[b * S_LEN + j0 + t] ? 0.f : NEG;
        cp_commit();
    };

    issue(0);

    for (int jt = 0; jt <= qb; jt++) {
        if (jt < qb) { issue(jt + 1); cp_wait1(); }
        else         { cp_wait0(); }
        __syncthreads();

        const int buf = jt & 1;
        const float*    vs = vbuf[buf];
        const uint32_t* ks = (const uint32_t*)kbuf[buf];
        const float*    mb = msb + buf * 64;

        float sc[8][4];
#pragma unroll
        for (int j = 0; j < 8; j++)
#pragma unroll
            for (int i = 0; i < 4; i++) sc[j][i] = 0.f;
#pragma unroll
        for (int kk = 0; kk < 8; kk++) {
#pragma unroll
            for (int j = 0; j < 8; j++) {
                const uint32_t* kr = ks + (8 * j + g) * FSTR + 8 * kk + tg;
                mma_tf32(sc[j][0], sc[j][1], sc[j][2], sc[j][3],
                         qf[kk][0], qf[kk][1], qf[kk][2], qf[kk][3],
                         kr[0], kr[4]);
            }
        }

        const bool diag = (jt == qb);
        const int rlo = wid * 16 + g, rhi = rlo + 8;
        float tm0 = -1e30f, tm1 = -1e30f;
#pragma unroll
        for (int j = 0; j < 8; j++) {
            const float2 mm = *(const float2*)&mb[8 * j + 2 * tg];
            float c0 = sc[j][0] + mm.x, c1 = sc[j][1] + mm.y;
            float c2 = sc[j][2] + mm.x, c3 = sc[j][3] + mm.y;
            if (diag) {
                const int kv = 8 * j + 2 * tg;
                c0 = (kv     > rlo) ? NEG : c0;
                c1 = (kv + 1 > rlo) ? NEG : c1;
                c2 = (kv     > rhi) ? NEG : c2;
                c3 = (kv + 1 > rhi) ? NEG : c3;
            }
            sc[j][0] = c0; sc[j][1] = c1; sc[j][2] = c2; sc[j][3] = c3;
            tm0 = fmaxf(tm0, fmaxf(c0, c1));
            tm1 = fmaxf(tm1, fmaxf(c2, c3));
        }
        tm0 = fmaxf(tm0, __shfl_xor_sync(0xffffffffu, tm0, 1));
        tm0 = fmaxf(tm0, __shfl_xor_sync(0xffffffffu, tm0, 2));
        tm1 = fmaxf(tm1, __shfl_xor_sync(0xffffffffu, tm1, 1));
        tm1 = fmaxf(tm1, __shfl_xor_sync(0xffffffffu, tm1, 2));

        const float mn0 = fmaxf(m0, tm0), mn1 = fmaxf(m1, tm1);
        const float al0 = __expf(m0 - mn0), al1 = __expf(m1 - mn1);
        float s0 = 0.f, s1 = 0.f;
#pragma unroll
        for (int j = 0; j < 8; j++) {
            sc[j][0] = __expf(sc[j][0] - mn0);
            sc[j][1] = __expf(sc[j][1] - mn0);
            sc[j][2] = __expf(sc[j][2] - mn1);
            sc[j][3] = __expf(sc[j][3] - mn1);
            s0 += sc[j][0] + sc[j][1];
            s1 += sc[j][2] + sc[j][3];
        }
        s0 += __shfl_xor_sync(0xffffffffu, s0, 1);
        s0 += __shfl_xor_sync(0xffffffffu, s0, 2);
        s1 += __shfl_xor_sync(0xffffffffu, s1, 1);
        s1 += __shfl_xor_sync(0xffffffffu, s1, 2);
        l0 = l0 * al0 + s0; l1 = l1 * al1 + s1;
        m0 = mn0; m1 = mn1;
#pragma unroll
        for (int j = 0; j < 8; j++) {
            oa[j][0] *= al0; oa[j][1] *= al0;
            oa[j][2] *= al1; oa[j][3] *= al1;
        }

#pragma unroll
        for (int kk = 0; kk < 4; kk++) {
            const uint32_t a0 = packh2(sc[2 * kk][0],     sc[2 * kk][1]);
            const uint32_t a1 = packh2(sc[2 * kk][2],     sc[2 * kk][3]);
            const uint32_t a2 = packh2(sc[2 * kk + 1][0], sc[2 * kk + 1][1]);
            const uint32_t a3 = packh2(sc[2 * kk + 1][2], sc[2 * kk + 1][3]);
            const float* vk = vs + (16 * kk + 2 * tg) * FSTR + g;
#pragma unroll
            for (int j2 = 0; j2 < 8; j2++) {
                const float* vc = vk + 8 * j2;
                const uint32_t b0 = packh2(vc[0],        vc[FSTR]);
                const uint32_t b1 = packh2(vc[8 * FSTR], vc[9 * FSTR]);
                mma_f16(oa[j2][0], oa[j2][1], oa[j2][2], oa[j2][3],
                        a0, a1, a2, a3, b0, b1);
            }
        }
        __syncthreads();
    }

    const float i0 = 1.f / l0, i1 = 1.f / l1;
    float* olo = g_ctx + ((size_t)(b * S_LEN) + qrlo) * EMB + h * 64;
    float* ohi = olo + (size_t)8 * EMB;
#pragma unroll
    for (int j2 = 0; j2 < 8; j2++) {
        const int d = 8 * j2 + 2 * tg;
        *(float2*)&olo[d] = make_float2(oa[j2][0] * i0, oa[j2][1] * i0);
        *(float2*)&ohi[d] = make_float2(oa[j2][2] * i1, oa[j2][3] * i1);
    }
}

// =============================== Launch ====================================
extern "C" void kernel_launch(void* const* d_in, const int* in_sizes, int n_in,
                              void* d_out, int out_size)
{
    const float* X     = (const float*)d_in[0];
    const int*   amask = (const int*)  d_in[1];
    const float* Wa    = (const float*)d_in[2];
    const float* ba    = (const float*)d_in[3];
    const float* Wp    = (const float*)d_in[4];
    const float* bp    = (const float*)d_in[5];
    float* out = (float*)d_out;

    cudaFuncSetAttribute(gemm_mma, cudaFuncAttributeMaxDynamicSharedMemorySize,
                         GEMM_SMEM);
    cudaFuncSetAttribute(flash_tc, cudaFuncAttributeMaxDynamicSharedMemorySize,
                         FLASH_SMEM);

    // 1) qkv = X @ Wa^T + ba   -> g_qkv
    {
        dim3 grid(3 * EMB / GBN, MTOT / GBM);
        gemm_mma<<<grid, 256, GEMM_SMEM>>>(X, Wa, ba, nullptr, MTOT, 3 * EMB, EMB);
    }
    // 2) attention -> g_ctx
    {
        dim3 grid(S_LEN / 64, NH, BATCH);
        flash_tc<<<grid, 128, FLASH_SMEM>>>(amask);
    }
    // 3) out = ctx @ Wp^T + bp
    {
        dim3 grid(EMB / GBN, MTOT / GBM);
        gemm_mma<<<grid, 256, GEMM_SMEM>>>(nullptr, Wp, bp, out, MTOT, EMB, EMB);
    }
}

// round 8
// speedup vs baseline: 4.0933x; 1.0034x over previous
#include <cuda_runtime.h>
#include <cstdint>

#define S_LEN 2048
#define EMB   1024
#define NH    16
#define HD    64
#define BATCH 2
#define MTOT  (BATCH * S_LEN)   // 4096
#define NEG   (-10000.0f)

// Scratch (allocation-free: __device__ globals)
__device__ float g_qkv[(size_t)MTOT * 3 * EMB];  // [4096, 3072] : q|k|v
__device__ float g_ctx[(size_t)MTOT * EMB];      // [4096, 1024] : [B,S,H,D]

// ============================ helpers ======================================
__device__ __forceinline__ uint32_t smem_u32(const void* p) {
    uint32_t a;
    asm("{ .reg .u64 t; cvta.to.shared.u64 t, %1; cvt.u32.u64 %0, t; }"
        : "=r"(a) : "l"(p));
    return a;
}
__device__ __forceinline__ uint32_t f2tf32(float v) {
    uint32_t r;
    asm("cvt.rna.tf32.f32 %0, %1;" : "=r"(r) : "f"(v));
    return r;
}
// pack two fp32 -> f16x2, lo in low half
__device__ __forceinline__ uint32_t packh2(float lo, float hi) {
    uint32_t r;
    asm("cvt.rn.f16x2.f32 %0, %1, %2;" : "=r"(r) : "f"(hi), "f"(lo));
    return r;
}
__device__ __forceinline__ void mma_tf32(float& c0, float& c1, float& c2, float& c3,
                                         uint32_t a0, uint32_t a1, uint32_t a2, uint32_t a3,
                                         uint32_t b0, uint32_t b1) {
    asm volatile(
        "mma.sync.aligned.m16n8k8.row.col.f32.tf32.tf32.f32 "
        "{%0,%1,%2,%3}, {%4,%5,%6,%7}, {%8,%9}, {%0,%1,%2,%3};"
        : "+f"(c0), "+f"(c1), "+f"(c2), "+f"(c3)
        : "r"(a0), "r"(a1), "r"(a2), "r"(a3), "r"(b0), "r"(b1));
}
__device__ __forceinline__ void mma_f16(float& c0, float& c1, float& c2, float& c3,
                                        uint32_t a0, uint32_t a1, uint32_t a2, uint32_t a3,
                                        uint32_t b0, uint32_t b1) {
    asm volatile(
        "mma.sync.aligned.m16n8k16.row.col.f32.f16.f16.f32 "
        "{%0,%1,%2,%3}, {%4,%5,%6,%7}, {%8,%9}, {%0,%1,%2,%3};"
        : "+f"(c0), "+f"(c1), "+f"(c2), "+f"(c3)
        : "r"(a0), "r"(a1), "r"(a2), "r"(a3), "r"(b0), "r"(b1));
}
__device__ __forceinline__ void cp_async16(uint32_t dst, const void* src) {
    asm volatile("cp.async.cg.shared.global [%0], [%1], 16;" :: "r"(dst), "l"(src));
}
__device__ __forceinline__ void cp_commit() {
    asm volatile("cp.async.commit_group;" ::: "memory");
}
__device__ __forceinline__ void cp_wait1() {
    asm volatile("cp.async.wait_group 1;" ::: "memory");
}
__device__ __forceinline__ void cp_wait0() {
    asm volatile("cp.async.wait_group 0;" ::: "memory");
}
// half-ulp rounding for fp32-bits -> tf32 truncation inside mma
#define RND 0x1000u

// ============ tf32 mma.sync GEMM (NT), 3-stage single-sync pipeline ========
// C[M,N] = A[M,K] @ B[N,K]^T + bias[N]
// CTA 128x128, BK=32, 256 threads, warp tile 64x32.
// Mainloop: wait(ck) -> sync -> issue(ck+2) -> compute(ck). One barrier/chunk,
// two chunk-times of cp.async prefetch distance.
#define GBM 128
#define GBN 128
#define GBK 32
#define STR 36                       // padded row stride (16B-aligned: 144B)
#define TSZ (GBM * STR)              // floats per operand tile per stage
#define NSTG 3
#define GEMM_SMEM (NSTG * 2 * TSZ * 4)  // 3 stages x (A+B) = 108 KB

__global__ void __launch_bounds__(256, 2)
gemm_mma(const float* __restrict__ A_, const float* __restrict__ Bw,
         const float* __restrict__ bias, float* __restrict__ C_,
         int M, int N, int K)
{
    const float* A = A_ ? A_ : g_ctx;
    float* C = C_ ? C_ : g_qkv;

    extern __shared__ uint32_t gsm[];
    uint32_t* const As = gsm;                 // [NSTG][TSZ]
    uint32_t* const Bs = gsm + NSTG * TSZ;    // [NSTG][TSZ]

    const int t = threadIdx.x;
    const int warp = t >> 5, lane = t & 31;
    const int wr = warp >> 2, wc = warp & 3;     // warp grid 2x4
    const int gid = lane >> 2, tig = lane & 3;
    const int bm = blockIdx.y * GBM, bn = blockIdx.x * GBN;
    const int lr = t >> 3, lc = (t & 7) * 4;     // cp.async mapping

    float acc[4][4][4];
#pragma unroll
    for (int mt = 0; mt < 4; mt++)
#pragma unroll
        for (int nt = 0; nt < 4; nt++)
#pragma unroll
            for (int i = 0; i < 4; i++) acc[mt][nt][i] = 0.f;

    const int nCk = K / GBK;

    auto issue = [&](int ck) {
        const int s = ck % NSTG;
        const int koff = ck * GBK;
#pragma unroll
        for (int u = 0; u < 4; u++) {
            const int r = lr + 32 * u;
            cp_async16(smem_u32(&As[s * TSZ + r * STR + lc]),
                       A + (size_t)(bm + r) * K + koff + lc);
            cp_async16(smem_u32(&Bs[s * TSZ + r * STR + lc]),
                       Bw + (size_t)(bn + r) * K + koff + lc);
        }
        cp_commit();
    };

    issue(0);
    issue(1);

    for (int ck = 0; ck < nCk; ++ck) {
        const int rem = nCk - 1 - ck;
        if (rem >= 1) cp_wait1();   // pending = {ck, ck+1}: ck landed
        else          cp_wait0();
        __syncthreads();            // all warps done with stage (ck-1)%NSTG
        if (rem >= 2) issue(ck + 2);

        const uint32_t* as = As + (ck % NSTG) * TSZ;
        const uint32_t* bs = Bs + (ck % NSTG) * TSZ;
#pragma unroll
        for (int k0 = 0; k0 < GBK; k0 += 8) {
            uint32_t bf[4][2];
#pragma unroll
            for (int nt = 0; nt < 4; nt++) {
                const int n = wc * 32 + nt * 8 + gid;
                bf[nt][0] = bs[n * STR + k0 + tig] + RND;
                bf[nt][1] = bs[n * STR + k0 + tig + 4] + RND;
            }
#pragma unroll
            for (int mt = 0; mt < 4; mt++) {
                const int r = wr * 64 + mt * 16 + gid;
                const uint32_t a0 = as[r * STR + k0 + tig] + RND;
                const uint32_t a1 = as[(r + 8) * STR + k0 + tig] + RND;
                const uint32_t a2 = as[r * STR + k0 + tig + 4] + RND;
                const uint32_t a3 = as[(r + 8) * STR + k0 + tig + 4] + RND;
#pragma unroll
                for (int nt = 0; nt < 4; nt++)
                    mma_tf32(acc[mt][nt][0], acc[mt][nt][1],
                             acc[mt][nt][2], acc[mt][nt][3],
                             a0, a1, a2, a3, bf[nt][0], bf[nt][1]);
            }
        }
    }

    // epilogue: C = acc + bias
#pragma unroll
    for (int mt = 0; mt < 4; mt++) {
        const int row0 = bm + wr * 64 + mt * 16 + gid;
#pragma unroll
        for (int nt = 0; nt < 4; nt++) {
            const int col = bn + wc * 32 + nt * 8 + tig * 2;
            const float b0 = bias[col], b1 = bias[col + 1];
            float2 v0 = make_float2(acc[mt][nt][0] + b0, acc[mt][nt][1] + b1);
            float2 v1 = make_float2(acc[mt][nt][2] + b0, acc[mt][nt][3] + b1);
            *(float2*)&C[(size_t)row0 * N + col] = v0;
            *(float2*)&C[(size_t)(row0 + 8) * N + col] = v1;
        }
    }
}

// ================= Tensor-core flash attention (R6, unchanged) =============
#define FSTR 68
#define FTILE (64 * FSTR)
#define FLASH_SMEM ((4 * FTILE + 128) * 4)

__global__ void __launch_bounds__(128)
flash_tc(const int* __restrict__ amask)
{
    extern __shared__ float fsm[];
    const int qb = 31 - (int)blockIdx.x;
    const int h  = blockIdx.y;
    const int b  = blockIdx.z;
    const int t  = threadIdx.x;
    const int wid = t >> 5, lane = t & 31;
    const int g = lane >> 2, tg = lane & 3;

    float* const kbuf[2] = { fsm,             fsm + 2 * FTILE };
    float* const vbuf[2] = { fsm + FTILE,     fsm + 3 * FTILE };
    float* const msb     = fsm + 4 * FTILE;

    const int qrlo = qb * 64 + wid * 16 + g;
    const float* qlo = g_qkv + ((size_t)(b * S_LEN) + qrlo) * 3072 + h * 64;
    const float* qhi = qlo + (size_t)8 * 3072;
    uint32_t qf[8][4];
#pragma unroll
    for (int kk = 0; kk < 8; kk++) {
        qf[kk][0] = f2tf32(qlo[8 * kk + tg] * 0.125f);
        qf[kk][1] = f2tf32(qhi[8 * kk + tg] * 0.125f);
        qf[kk][2] = f2tf32(qlo[8 * kk + tg + 4] * 0.125f);
        qf[kk][3] = f2tf32(qhi[8 * kk + tg + 4] * 0.125f);
    }

    float oa[8][4];
#pragma unroll
    for (int j = 0; j < 8; j++)
#pragma unroll
        for (int i = 0; i < 4; i++) oa[j][i] = 0.f;
    float m0 = -1e30f, m1 = -1e30f, l0 = 0.f, l1 = 0.f;

    auto issue = [&](int jt) {
        const int buf = jt & 1;
        float* ks = kbuf[buf];
        float* vs = vbuf[buf];
        const int j0 = jt * 64;
#pragma unroll
        for (int u = 0; u < 8; u++) {
            const int idx = t + 128 * u;
            const int r = idx >> 4, c4 = (idx & 15) * 4;
            const float* src = g_qkv + ((size_t)(b * S_LEN) + j0 + r) * 3072
                               + 1024 + h * 64 + c4;
            cp_async16(smem_u32(ks + r * FSTR + c4), src);
            cp_async16(smem_u32(vs + r * FSTR + c4), src + 1024);
        }
        if (t < 64)
            msb[buf * 64 + t] = amask[b * S_LEN + j0 + t] ? 0.f : NEG;
        cp_commit();
    };

    issue(0);

    for (int jt = 0; jt <= qb; jt++) {
        if (jt < qb) { issue(jt + 1); cp_wait1(); }
        else         { cp_wait0(); }
        __syncthreads();

        const int buf = jt & 1;
        const float*    vs = vbuf[buf];
        const uint32_t* ks = (const uint32_t*)kbuf[buf];
        const float*    mb = msb + buf * 64;

        float sc[8][4];
#pragma unroll
        for (int j = 0; j < 8; j++)
#pragma unroll
            for (int i = 0; i < 4; i++) sc[j][i] = 0.f;
#pragma unroll
        for (int kk = 0; kk < 8; kk++) {
#pragma unroll
            for (int j = 0; j < 8; j++) {
                const uint32_t* kr = ks + (8 * j + g) * FSTR + 8 * kk + tg;
                mma_tf32(sc[j][0], sc[j][1], sc[j][2], sc[j][3],
                         qf[kk][0], qf[kk][1], qf[kk][2], qf[kk][3],
                         kr[0], kr[4]);
            }
        }

        const bool diag = (jt == qb);
        const int rlo = wid * 16 + g, rhi = rlo + 8;
        float tm0 = -1e30f, tm1 = -1e30f;
#pragma unroll
        for (int j = 0; j < 8; j++) {
            const float2 mm = *(const float2*)&mb[8 * j + 2 * tg];
            float c0 = sc[j][0] + mm.x, c1 = sc[j][1] + mm.y;
            float c2 = sc[j][2] + mm.x, c3 = sc[j][3] + mm.y;
            if (diag) {
                const int kv = 8 * j + 2 * tg;
                c0 = (kv     > rlo) ? NEG : c0;
                c1 = (kv + 1 > rlo) ? NEG : c1;
                c2 = (kv     > rhi) ? NEG : c2;
                c3 = (kv + 1 > rhi) ? NEG : c3;
            }
            sc[j][0] = c0; sc[j][1] = c1; sc[j][2] = c2; sc[j][3] = c3;
            tm0 = fmaxf(tm0, fmaxf(c0, c1));
            tm1 = fmaxf(tm1, fmaxf(c2, c3));
        }
        tm0 = fmaxf(tm0, __shfl_xor_sync(0xffffffffu, tm0, 1));
        tm0 = fmaxf(tm0, __shfl_xor_sync(0xffffffffu, tm0, 2));
        tm1 = fmaxf(tm1, __shfl_xor_sync(0xffffffffu, tm1, 1));
        tm1 = fmaxf(tm1, __shfl_xor_sync(0xffffffffu, tm1, 2));

        const float mn0 = fmaxf(m0, tm0), mn1 = fmaxf(m1, tm1);
        const float al0 = __expf(m0 - mn0), al1 = __expf(m1 - mn1);
        float s0 = 0.f, s1 = 0.f;
#pragma unroll
        for (int j = 0; j < 8; j++) {
            sc[j][0] = __expf(sc[j][0] - mn0);
            sc[j][1] = __expf(sc[j][1] - mn0);
            sc[j][2] = __expf(sc[j][2] - mn1);
            sc[j][3] = __expf(sc[j][3] - mn1);
            s0 += sc[j][0] + sc[j][1];
            s1 += sc[j][2] + sc[j][3];
        }
        s0 += __shfl_xor_sync(0xffffffffu, s0, 1);
        s0 += __shfl_xor_sync(0xffffffffu, s0, 2);
        s1 += __shfl_xor_sync(0xffffffffu, s1, 1);
        s1 += __shfl_xor_sync(0xffffffffu, s1, 2);
        l0 = l0 * al0 + s0; l1 = l1 * al1 + s1;
        m0 = mn0; m1 = mn1;
#pragma unroll
        for (int j = 0; j < 8; j++) {
            oa[j][0] *= al0; oa[j][1] *= al0;
            oa[j][2] *= al1; oa[j][3] *= al1;
        }

#pragma unroll
        for (int kk = 0; kk < 4; kk++) {
            const uint32_t a0 = packh2(sc[2 * kk][0],     sc[2 * kk][1]);
            const uint32_t a1 = packh2(sc[2 * kk][2],     sc[2 * kk][3]);
            const uint32_t a2 = packh2(sc[2 * kk + 1][0], sc[2 * kk + 1][1]);
            const uint32_t a3 = packh2(sc[2 * kk + 1][2], sc[2 * kk + 1][3]);
            const float* vk = vs + (16 * kk + 2 * tg) * FSTR + g;
#pragma unroll
            for (int j2 = 0; j2 < 8; j2++) {
                const float* vc = vk + 8 * j2;
                const uint32_t b0 = packh2(vc[0],        vc[FSTR]);
                const uint32_t b1 = packh2(vc[8 * FSTR], vc[9 * FSTR]);
                mma_f16(oa[j2][0], oa[j2][1], oa[j2][2], oa[j2][3],
                        a0, a1, a2, a3, b0, b1);
            }
        }
        __syncthreads();
    }

    const float i0 = 1.f / l0, i1 = 1.f / l1;
    float* olo = g_ctx + ((size_t)(b * S_LEN) + qrlo) * EMB + h * 64;
    float* ohi = olo + (size_t)8 * EMB;
#pragma unroll
    for (int j2 = 0; j2 < 8; j2++) {
        const int d = 8 * j2 + 2 * tg;
        *(float2*)&olo[d] = make_float2(oa[j2][0] * i0, oa[j2][1] * i0);
        *(float2*)&ohi[d] = make_float2(oa[j2][2] * i1, oa[j2][3] * i1);
    }
}

// =============================== Launch ====================================
extern "C" void kernel_launch(void* const* d_in, const int* in_sizes, int n_in,
                              void* d_out, int out_size)
{
    const float* X     = (const float*)d_in[0];
    const int*   amask = (const int*)  d_in[1];
    const float* Wa    = (const float*)d_in[2];
    const float* ba    = (const float*)d_in[3];
    const float* Wp    = (const float*)d_in[4];
    const float* bp    = (const float*)d_in[5];
    float* out = (float*)d_out;

    cudaFuncSetAttribute(gemm_mma, cudaFuncAttributeMaxDynamicSharedMemorySize,
                         GEMM_SMEM);
    cudaFuncSetAttribute(flash_tc, cudaFuncAttributeMaxDynamicSharedMemorySize,
                         FLASH_SMEM);

    // 1) qkv = X @ Wa^T + ba   -> g_qkv
    {
        dim3 grid(3 * EMB / GBN, MTOT / GBM);
        gemm_mma<<<grid, 256, GEMM_SMEM>>>(X, Wa, ba, nullptr, MTOT, 3 * EMB, EMB);
    }
    // 2) attention -> g_ctx
    {
        dim3 grid(S_LEN / 64, NH, BATCH);
        flash_tc<<<grid, 128, FLASH_SMEM>>>(amask);
    }
    // 3) out = ctx @ Wp^T + bp
    {
        dim3 grid(EMB / GBN, MTOT / GBM);
        gemm_mma<<<grid, 256, GEMM_SMEM>>>(nullptr, Wp, bp, out, MTOT, EMB, EMB);
    }
}

// round 9
// speedup vs baseline: 4.9291x; 1.2042x over previous
#include <cuda_runtime.h>
#include <cuda_fp16.h>
#include <cstdint>

#define S_LEN 2048
#define EMB   1024
#define NH    16
#define HD    64
#define BATCH 2
#define MTOT  (BATCH * S_LEN)   // 4096
#define NEG   (-10000.0f)

// Scratch (allocation-free: __device__ globals)
__device__ float g_qkv[(size_t)MTOT * 3 * EMB];                 // fp32 q|k|v
__device__ __align__(128) __half g_x16 [(size_t)MTOT * EMB];    // X in fp16
__device__ __align__(128) __half g_wa16[(size_t)3 * EMB * EMB]; // W_attn fp16
__device__ __align__(128) __half g_wp16[(size_t)EMB * EMB];     // W_proj fp16
__device__ __align__(128) __half g_ctx16[(size_t)MTOT * EMB];   // ctx fp16

// ============================ helpers ======================================
__device__ __forceinline__ uint32_t smem_u32(const void* p) {
    uint32_t a;
    asm("{ .reg .u64 t; cvta.to.shared.u64 t, %1; cvt.u32.u64 %0, t; }"
        : "=r"(a) : "l"(p));
    return a;
}
__device__ __forceinline__ uint32_t f2tf32(float v) {
    uint32_t r;
    asm("cvt.rna.tf32.f32 %0, %1;" : "=r"(r) : "f"(v));
    return r;
}
__device__ __forceinline__ uint32_t packh2(float lo, float hi) {
    uint32_t r;
    asm("cvt.rn.f16x2.f32 %0, %1, %2;" : "=r"(r) : "f"(hi), "f"(lo));
    return r;
}
__device__ __forceinline__ void mma_tf32(float& c0, float& c1, float& c2, float& c3,
                                         uint32_t a0, uint32_t a1, uint32_t a2, uint32_t a3,
                                         uint32_t b0, uint32_t b1) {
    asm volatile(
        "mma.sync.aligned.m16n8k8.row.col.f32.tf32.tf32.f32 "
        "{%0,%1,%2,%3}, {%4,%5,%6,%7}, {%8,%9}, {%0,%1,%2,%3};"
        : "+f"(c0), "+f"(c1), "+f"(c2), "+f"(c3)
        : "r"(a0), "r"(a1), "r"(a2), "r"(a3), "r"(b0), "r"(b1));
}
__device__ __forceinline__ void mma_f16(float& c0, float& c1, float& c2, float& c3,
                                        uint32_t a0, uint32_t a1, uint32_t a2, uint32_t a3,
                                        uint32_t b0, uint32_t b1) {
    asm volatile(
        "mma.sync.aligned.m16n8k16.row.col.f32.f16.f16.f32 "
        "{%0,%1,%2,%3}, {%4,%5,%6,%7}, {%8,%9}, {%0,%1,%2,%3};"
        : "+f"(c0), "+f"(c1), "+f"(c2), "+f"(c3)
        : "r"(a0), "r"(a1), "r"(a2), "r"(a3), "r"(b0), "r"(b1));
}
__device__ __forceinline__ void ldsm_x4(uint32_t& r0, uint32_t& r1,
                                        uint32_t& r2, uint32_t& r3, uint32_t addr) {
    asm volatile("ldmatrix.sync.aligned.m8n8.x4.shared.b16 {%0,%1,%2,%3}, [%4];"
                 : "=r"(r0), "=r"(r1), "=r"(r2), "=r"(r3) : "r"(addr));
}
__device__ __forceinline__ void cp_async16(uint32_t dst, const void* src) {
    asm volatile("cp.async.cg.shared.global [%0], [%1], 16;" :: "r"(dst), "l"(src));
}
__device__ __forceinline__ void cp_commit() {
    asm volatile("cp.async.commit_group;" ::: "memory");
}
__device__ __forceinline__ void cp_wait1() {
    asm volatile("cp.async.wait_group 1;" ::: "memory");
}
__device__ __forceinline__ void cp_wait0() {
    asm volatile("cp.async.wait_group 0;" ::: "memory");
}

// ====================== fp32 -> fp16 convert ===============================
__global__ void __launch_bounds__(256)
cvt_f2h(const float4* __restrict__ src, int n4, int which)
{
    __half2* dst = which == 0 ? (__half2*)g_x16
                 : which == 1 ? (__half2*)g_wa16 : (__half2*)g_wp16;
    const int i = blockIdx.x * blockDim.x + threadIdx.x;
    if (i < n4) {
        const float4 v = src[i];
        dst[2 * i]     = __floats2half2_rn(v.x, v.y);
        dst[2 * i + 1] = __floats2half2_rn(v.z, v.w);
    }
}

// ============ fp16 mma.sync GEMM (NT), 3-stage, ldmatrix ===================
// C[M,N] = A[M,K] @ B[N,K]^T + bias[N]   (A,B fp16; C fp32)
// CTA 128x128, BK=32, 256 threads, warp tile 64x32, m16n8k16.
// mode 0: A=g_x16, B=g_wa16, C=g_qkv | mode 1: A=g_ctx16, B=g_wp16, C=C_
#define GBM 128
#define GBN 128
#define GBK 32
#define SH  40                        // smem row stride (halves) = 80 B
#define HTSZ (GBM * SH)               // halves per operand tile per stage
#define NSTG 3
#define GEMM_SMEM (NSTG * 2 * HTSZ * 2)   // 61440 B

__global__ void __launch_bounds__(256, 2)
gemm_h(int mode, const float* __restrict__ bias, float* __restrict__ C_,
       int M, int N, int K)
{
    const __half* A  = mode == 0 ? g_x16  : g_ctx16;
    const __half* Bw = mode == 0 ? g_wa16 : g_wp16;
    float* C = mode == 0 ? g_qkv : C_;

    extern __shared__ __half hsm[];
    __half* const As = hsm;
    __half* const Bs = hsm + NSTG * HTSZ;

    const int t = threadIdx.x;
    const int warp = t >> 5, lane = t & 31;
    const int wr = warp >> 2, wc = warp & 3;     // warp grid 2x4
    const int gid = lane >> 2, tig = lane & 3;
    const int bm = blockIdx.y * GBM, bn = blockIdx.x * GBN;
    const int lr = t >> 1, lc = (t & 1) * 16;    // cp.async mapping (2 rows/thr pair)

    // ldmatrix per-lane offsets (halves):
    //   A x4: mat0 rows+0/k+0, mat1 rows+8/k+0, mat2 rows+0/k+8, mat3 rows+8/k+8
    //   B x4: mat0 n+0/k+0,    mat1 n+0/k+8,    mat2 n+8/k+0,    mat3 n+8/k+8
    const int a_loff = ((lane & 7) + ((lane >> 3) & 1) * 8) * SH + ((lane >> 4) & 1) * 8;
    const int b_loff = ((lane & 7) + ((lane >> 4) & 1) * 8) * SH + ((lane >> 3) & 1) * 8;

    float acc[4][4][4];
#pragma unroll
    for (int mt = 0; mt < 4; mt++)
#pragma unroll
        for (int nt = 0; nt < 4; nt++)
#pragma unroll
            for (int i = 0; i < 4; i++) acc[mt][nt][i] = 0.f;

    const int nCk = K / GBK;

    auto issue = [&](int ck) {
        const int s = ck % NSTG;
        const int koff = ck * GBK;
        const __half* ga = A  + (size_t)(bm + lr) * K + koff + lc;
        const __half* gb = Bw + (size_t)(bn + lr) * K + koff + lc;
        const uint32_t sa = smem_u32(As + s * HTSZ + lr * SH + lc);
        const uint32_t sb = smem_u32(Bs + s * HTSZ + lr * SH + lc);
        cp_async16(sa, ga);      cp_async16(sa + 16, ga + 8);
        cp_async16(sb, gb);      cp_async16(sb + 16, gb + 8);
        cp_commit();
    };

    issue(0);
    issue(1);

    for (int ck = 0; ck < nCk; ++ck) {
        const int rem = nCk - 1 - ck;
        if (rem >= 1) cp_wait1();
        else          cp_wait0();
        __syncthreads();
        if (rem >= 2) issue(ck + 2);

        const uint32_t as0 = smem_u32(As + (ck % NSTG) * HTSZ);
        const uint32_t bs0 = smem_u32(Bs + (ck % NSTG) * HTSZ);
#pragma unroll
        for (int k0 = 0; k0 < GBK; k0 += 16) {
            uint32_t bf[4][2];
#pragma unroll
            for (int np = 0; np < 2; np++) {
                const uint32_t addr =
                    bs0 + 2 * (b_loff + (wc * 32 + np * 16) * SH + k0);
                ldsm_x4(bf[2 * np][0], bf[2 * np][1],
                        bf[2 * np + 1][0], bf[2 * np + 1][1], addr);
            }
#pragma unroll
            for (int mt = 0; mt < 4; mt++) {
                uint32_t a0, a1, a2, a3;
                const uint32_t addr =
                    as0 + 2 * (a_loff + (wr * 64 + mt * 16) * SH + k0);
                ldsm_x4(a0, a1, a2, a3, addr);
#pragma unroll
                for (int nt = 0; nt < 4; nt++)
                    mma_f16(acc[mt][nt][0], acc[mt][nt][1],
                            acc[mt][nt][2], acc[mt][nt][3],
                            a0, a1, a2, a3, bf[nt][0], bf[nt][1]);
            }
        }
    }

    // epilogue: C = acc + bias
#pragma unroll
    for (int mt = 0; mt < 4; mt++) {
        const int row0 = bm + wr * 64 + mt * 16 + gid;
#pragma unroll
        for (int nt = 0; nt < 4; nt++) {
            const int col = bn + wc * 32 + nt * 8 + tig * 2;
            const float b0 = bias[col], b1 = bias[col + 1];
            float2 v0 = make_float2(acc[mt][nt][0] + b0, acc[mt][nt][1] + b1);
            float2 v1 = make_float2(acc[mt][nt][2] + b0, acc[mt][nt][3] + b1);
            *(float2*)&C[(size_t)row0 * N + col] = v0;
            *(float2*)&C[(size_t)(row0 + 8) * N + col] = v1;
        }
    }
}

// ================= Tensor-core flash attention =============================
// (R6 design; epilogue now writes fp16 ctx for the fp16 proj GEMM)
#define FSTR 68
#define FTILE (64 * FSTR)
#define FLASH_SMEM ((4 * FTILE + 128) * 4)

__global__ void __launch_bounds__(128)
flash_tc(const int* __restrict__ amask)
{
    extern __shared__ float fsm[];
    const int qb = 31 - (int)blockIdx.x;
    const int h  = blockIdx.y;
    const int b  = blockIdx.z;
    const int t  = threadIdx.x;
    const int wid = t >> 5, lane = t & 31;
    const int g = lane >> 2, tg = lane & 3;

    float* const kbuf[2] = { fsm,             fsm + 2 * FTILE };
    float* const vbuf[2] = { fsm + FTILE,     fsm + 3 * FTILE };
    float* const msb     = fsm + 4 * FTILE;

    const int qrlo = qb * 64 + wid * 16 + g;
    const float* qlo = g_qkv + ((size_t)(b * S_LEN) + qrlo) * 3072 + h * 64;
    const float* qhi = qlo + (size_t)8 * 3072;
    uint32_t qf[8][4];
#pragma unroll
    for (int kk = 0; kk < 8; kk++) {
        qf[kk][0] = f2tf32(qlo[8 * kk + tg] * 0.125f);
        qf[kk][1] = f2tf32(qhi[8 * kk + tg] * 0.125f);
        qf[kk][2] = f2tf32(qlo[8 * kk + tg + 4] * 0.125f);
        qf[kk][3] = f2tf32(qhi[8 * kk + tg + 4] * 0.125f);
    }

    float oa[8][4];
#pragma unroll
    for (int j = 0; j < 8; j++)
#pragma unroll
        for (int i = 0; i < 4; i++) oa[j][i] = 0.f;
    float m0 = -1e30f, m1 = -1e30f, l0 = 0.f, l1 = 0.f;

    auto issue = [&](int jt) {
        const int buf = jt & 1;
        float* ks = kbuf[buf];
        float* vs = vbuf[buf];
        const int j0 = jt * 64;
#pragma unroll
        for (int u = 0; u < 8; u++) {
            const int idx = t + 128 * u;
            const int r = idx >> 4, c4 = (idx & 15) * 4;
            const float* src = g_qkv + ((size_t)(b * S_LEN) + j0 + r) * 3072
                               + 1024 + h * 64 + c4;
            cp_async16(smem_u32(ks + r * FSTR + c4), src);
            cp_async16(smem_u32(vs + r * FSTR + c4), src + 1024);
        }
        if (t < 64)
            msb[buf * 64 + t] = amask[b * S_LEN + j0 + t] ? 0.f : NEG;
        cp_commit();
    };

    issue(0);

    for (int jt = 0; jt <= qb; jt++) {
        if (jt < qb) { issue(jt + 1); cp_wait1(); }
        else         { cp_wait0(); }
        __syncthreads();

        const int buf = jt & 1;
        const float*    vs = vbuf[buf];
        const uint32_t* ks = (const uint32_t*)kbuf[buf];
        const float*    mb = msb + buf * 64;

        float sc[8][4];
#pragma unroll
        for (int j = 0; j < 8; j++)
#pragma unroll
            for (int i = 0; i < 4; i++) sc[j][i] = 0.f;
#pragma unroll
        for (int kk = 0; kk < 8; kk++) {
#pragma unroll
            for (int j = 0; j < 8; j++) {
                const uint32_t* kr = ks + (8 * j + g) * FSTR + 8 * kk + tg;
                mma_tf32(sc[j][0], sc[j][1], sc[j][2], sc[j][3],
                         qf[kk][0], qf[kk][1], qf[kk][2], qf[kk][3],
                         kr[0], kr[4]);
            }
        }

        const bool diag = (jt == qb);
        const int rlo = wid * 16 + g, rhi = rlo + 8;
        float tm0 = -1e30f, tm1 = -1e30f;
#pragma unroll
        for (int j = 0; j < 8; j++) {
            const float2 mm = *(const float2*)&mb[8 * j + 2 * tg];
            float c0 = sc[j][0] + mm.x, c1 = sc[j][1] + mm.y;
            float c2 = sc[j][2] + mm.x, c3 = sc[j][3] + mm.y;
            if (diag) {
                const int kv = 8 * j + 2 * tg;
                c0 = (kv     > rlo) ? NEG : c0;
                c1 = (kv + 1 > rlo) ? NEG : c1;
                c2 = (kv     > rhi) ? NEG : c2;
                c3 = (kv + 1 > rhi) ? NEG : c3;
            }
            sc[j][0] = c0; sc[j][1] = c1; sc[j][2] = c2; sc[j][3] = c3;
            tm0 = fmaxf(tm0, fmaxf(c0, c1));
            tm1 = fmaxf(tm1, fmaxf(c2, c3));
        }
        tm0 = fmaxf(tm0, __shfl_xor_sync(0xffffffffu, tm0, 1));
        tm0 = fmaxf(tm0, __shfl_xor_sync(0xffffffffu, tm0, 2));
        tm1 = fmaxf(tm1, __shfl_xor_sync(0xffffffffu, tm1, 1));
        tm1 = fmaxf(tm1, __shfl_xor_sync(0xffffffffu, tm1, 2));

        const float mn0 = fmaxf(m0, tm0), mn1 = fmaxf(m1, tm1);
        const float al0 = __expf(m0 - mn0), al1 = __expf(m1 - mn1);
        float s0 = 0.f, s1 = 0.f;
#pragma unroll
        for (int j = 0; j < 8; j++) {
            sc[j][0] = __expf(sc[j][0] - mn0);
            sc[j][1] = __expf(sc[j][1] - mn0);
            sc[j][2] = __expf(sc[j][2] - mn1);
            sc[j][3] = __expf(sc[j][3] - mn1);
            s0 += sc[j][0] + sc[j][1];
            s1 += sc[j][2] + sc[j][3];
        }
        s0 += __shfl_xor_sync(0xffffffffu, s0, 1);
        s0 += __shfl_xor_sync(0xffffffffu, s0, 2);
        s1 += __shfl_xor_sync(0xffffffffu, s1, 1);
        s1 += __shfl_xor_sync(0xffffffffu, s1, 2);
        l0 = l0 * al0 + s0; l1 = l1 * al1 + s1;
        m0 = mn0; m1 = mn1;
#pragma unroll
        for (int j = 0; j < 8; j++) {
            oa[j][0] *= al0; oa[j][1] *= al0;
            oa[j][2] *= al1; oa[j][3] *= al1;
        }

#pragma unroll
        for (int kk = 0; kk < 4; kk++) {
            const uint32_t a0 = packh2(sc[2 * kk][0],     sc[2 * kk][1]);
            const uint32_t a1 = packh2(sc[2 * kk][2],     sc[2 * kk][3]);
            const uint32_t a2 = packh2(sc[2 * kk + 1][0], sc[2 * kk + 1][1]);
            const uint32_t a3 = packh2(sc[2 * kk + 1][2], sc[2 * kk + 1][3]);
            const float* vk = vs + (16 * kk + 2 * tg) * FSTR + g;
#pragma unroll
            for (int j2 = 0; j2 < 8; j2++) {
                const float* vc = vk + 8 * j2;
                const uint32_t b0 = packh2(vc[0],        vc[FSTR]);
                const uint32_t b1 = packh2(vc[8 * FSTR], vc[9 * FSTR]);
                mma_f16(oa[j2][0], oa[j2][1], oa[j2][2], oa[j2][3],
                        a0, a1, a2, a3, b0, b1);
            }
        }
        __syncthreads();
    }

    // epilogue -> fp16 ctx
    const float i0 = 1.f / l0, i1 = 1.f / l1;
    __half2* olo = (__half2*)(g_ctx16 + ((size_t)(b * S_LEN) + qrlo) * EMB + h * 64);
    __half2* ohi = (__half2*)((__half*)olo + (size_t)8 * EMB);
#pragma unroll
    for (int j2 = 0; j2 < 8; j2++) {
        const int d2 = 4 * j2 + tg;   // half2 index of d = 8*j2 + 2*tg
        olo[d2] = __floats2half2_rn(oa[j2][0] * i0, oa[j2][1] * i0);
        ohi[d2] = __floats2half2_rn(oa[j2][2] * i1, oa[j2][3] * i1);
    }
}

// =============================== Launch ====================================
extern "C" void kernel_launch(void* const* d_in, const int* in_sizes, int n_in,
                              void* d_out, int out_size)
{
    const float* X     = (const float*)d_in[0];
    const int*   amask = (const int*)  d_in[1];
    const float* Wa    = (const float*)d_in[2];
    const float* ba    = (const float*)d_in[3];
    const float* Wp    = (const float*)d_in[4];
    const float* bp    = (const float*)d_in[5];
    float* out = (float*)d_out;

    cudaFuncSetAttribute(gemm_h, cudaFuncAttributeMaxDynamicSharedMemorySize,
                         GEMM_SMEM);
    cudaFuncSetAttribute(flash_tc, cudaFuncAttributeMaxDynamicSharedMemorySize,
                         FLASH_SMEM);

    // 0) convert inputs to fp16
    {
        const int nx = MTOT * EMB / 4, na = 3 * EMB * EMB / 4, np = EMB * EMB / 4;
        cvt_f2h<<<(nx + 255) / 256, 256>>>((const float4*)X, nx, 0);
        cvt_f2h<<<(na + 255) / 256, 256>>>((const float4*)Wa, na, 1);
        cvt_f2h<<<(np + 255) / 256, 256>>>((const float4*)Wp, np, 2);
    }
    // 1) qkv = X @ Wa^T + ba   -> g_qkv (fp32)
    {
        dim3 grid(3 * EMB / GBN, MTOT / GBM);
        gemm_h<<<grid, 256, GEMM_SMEM>>>(0, ba, nullptr, MTOT, 3 * EMB, EMB);
    }
    // 2) attention -> g_ctx16 (fp16)
    {
        dim3 grid(S_LEN / 64, NH, BATCH);
        flash_tc<<<grid, 128, FLASH_SMEM>>>(amask);
    }
    // 3) out = ctx @ Wp^T + bp
    {
        dim3 grid(EMB / GBN, MTOT / GBM);
        gemm_h<<<grid, 256, GEMM_SMEM>>>(1, bp, out, MTOT, EMB, EMB);
    }
}

// round 10
// speedup vs baseline: 7.0375x; 1.4277x over previous
#include <cuda_runtime.h>
#include <cuda_fp16.h>
#include <cstdint>

#define S_LEN 2048
#define EMB   1024
#define NH    16
#define HD    64
#define BATCH 2
#define MTOT  (BATCH * S_LEN)   // 4096
#define NEG   (-10000.0f)

// Scratch (allocation-free: __device__ globals)
__device__ __align__(128) __half g_qkv16[(size_t)MTOT * 3 * EMB]; // q|k|v fp16
__device__ __align__(128) __half g_x16 [(size_t)MTOT * EMB];      // X fp16
__device__ __align__(128) __half g_wa16[(size_t)3 * EMB * EMB];   // W_attn fp16
__device__ __align__(128) __half g_wp16[(size_t)EMB * EMB];       // W_proj fp16
__device__ __align__(128) __half g_ctx16[(size_t)MTOT * EMB];     // ctx fp16

// ============================ helpers ======================================
__device__ __forceinline__ uint32_t smem_u32(const void* p) {
    uint32_t a;
    asm("{ .reg .u64 t; cvta.to.shared.u64 t, %1; cvt.u32.u64 %0, t; }"
        : "=r"(a) : "l"(p));
    return a;
}
__device__ __forceinline__ uint32_t packh2(float lo, float hi) {
    uint32_t r;
    asm("cvt.rn.f16x2.f32 %0, %1, %2;" : "=r"(r) : "f"(hi), "f"(lo));
    return r;
}
__device__ __forceinline__ void mma_f16(float& c0, float& c1, float& c2, float& c3,
                                        uint32_t a0, uint32_t a1, uint32_t a2, uint32_t a3,
                                        uint32_t b0, uint32_t b1) {
    asm volatile(
        "mma.sync.aligned.m16n8k16.row.col.f32.f16.f16.f32 "
        "{%0,%1,%2,%3}, {%4,%5,%6,%7}, {%8,%9}, {%0,%1,%2,%3};"
        : "+f"(c0), "+f"(c1), "+f"(c2), "+f"(c3)
        : "r"(a0), "r"(a1), "r"(a2), "r"(a3), "r"(b0), "r"(b1));
}
__device__ __forceinline__ void ldsm_x4(uint32_t& r0, uint32_t& r1,
                                        uint32_t& r2, uint32_t& r3, uint32_t addr) {
    asm volatile("ldmatrix.sync.aligned.m8n8.x4.shared.b16 {%0,%1,%2,%3}, [%4];"
                 : "=r"(r0), "=r"(r1), "=r"(r2), "=r"(r3) : "r"(addr));
}
__device__ __forceinline__ void ldsm_x4_t(uint32_t& r0, uint32_t& r1,
                                          uint32_t& r2, uint32_t& r3, uint32_t addr) {
    asm volatile("ldmatrix.sync.aligned.m8n8.x4.trans.shared.b16 {%0,%1,%2,%3}, [%4];"
                 : "=r"(r0), "=r"(r1), "=r"(r2), "=r"(r3) : "r"(addr));
}
__device__ __forceinline__ void cp_async16(uint32_t dst, const void* src) {
    asm volatile("cp.async.cg.shared.global [%0], [%1], 16;" :: "r"(dst), "l"(src));
}
__device__ __forceinline__ void cp_commit() {
    asm volatile("cp.async.commit_group;" ::: "memory");
}
__device__ __forceinline__ void cp_wait1() {
    asm volatile("cp.async.wait_group 1;" ::: "memory");
}
__device__ __forceinline__ void cp_wait0() {
    asm volatile("cp.async.wait_group 0;" ::: "memory");
}

// ====================== fp32 -> fp16 convert ===============================
__global__ void __launch_bounds__(256)
cvt_f2h(const float4* __restrict__ src, int n4, int which)
{
    __half2* dst = which == 0 ? (__half2*)g_x16
                 : which == 1 ? (__half2*)g_wa16 : (__half2*)g_wp16;
    const int i = blockIdx.x * blockDim.x + threadIdx.x;
    if (i < n4) {
        const float4 v = src[i];
        dst[2 * i]     = __floats2half2_rn(v.x, v.y);
        dst[2 * i + 1] = __floats2half2_rn(v.z, v.w);
    }
}

// ============ fp16 mma.sync GEMM (NT), 3-stage, ldmatrix ===================
// mode 0: A=g_x16, B=g_wa16, C=g_qkv16 (fp16) | mode 1: A=g_ctx16, B=g_wp16,
// C=C_ (fp32). CTA 128x128, BK=32, 256 threads, warp tile 64x32, m16n8k16.
#define GBM 128
#define GBN 128
#define GBK 32
#define SH  40
#define HTSZ (GBM * SH)
#define NSTG 3
#define GEMM_SMEM (NSTG * 2 * HTSZ * 2)   // 61440 B

__global__ void __launch_bounds__(256, 2)
gemm_h(int mode, const float* __restrict__ bias, float* __restrict__ C_,
       int M, int N, int K)
{
    const __half* A  = mode == 0 ? g_x16  : g_ctx16;
    const __half* Bw = mode == 0 ? g_wa16 : g_wp16;

    extern __shared__ __half hsm[];
    __half* const As = hsm;
    __half* const Bs = hsm + NSTG * HTSZ;

    const int t = threadIdx.x;
    const int warp = t >> 5, lane = t & 31;
    const int wr = warp >> 2, wc = warp & 3;
    const int gid = lane >> 2, tig = lane & 3;
    const int bm = blockIdx.y * GBM, bn = blockIdx.x * GBN;
    const int lr = t >> 1, lc = (t & 1) * 16;

    const int a_loff = ((lane & 7) + ((lane >> 3) & 1) * 8) * SH + ((lane >> 4) & 1) * 8;
    const int b_loff = ((lane & 7) + ((lane >> 4) & 1) * 8) * SH + ((lane >> 3) & 1) * 8;

    float acc[4][4][4];
#pragma unroll
    for (int mt = 0; mt < 4; mt++)
#pragma unroll
        for (int nt = 0; nt < 4; nt++)
#pragma unroll
            for (int i = 0; i < 4; i++) acc[mt][nt][i] = 0.f;

    const int nCk = K / GBK;

    auto issue = [&](int ck) {
        const int s = ck % NSTG;
        const int koff = ck * GBK;
        const __half* ga = A  + (size_t)(bm + lr) * K + koff + lc;
        const __half* gb = Bw + (size_t)(bn + lr) * K + koff + lc;
        const uint32_t sa = smem_u32(As + s * HTSZ + lr * SH + lc);
        const uint32_t sb = smem_u32(Bs + s * HTSZ + lr * SH + lc);
        cp_async16(sa, ga);      cp_async16(sa + 16, ga + 8);
        cp_async16(sb, gb);      cp_async16(sb + 16, gb + 8);
        cp_commit();
    };

    issue(0);
    issue(1);

    for (int ck = 0; ck < nCk; ++ck) {
        const int rem = nCk - 1 - ck;
        if (rem >= 1) cp_wait1();
        else          cp_wait0();
        __syncthreads();
        if (rem >= 2) issue(ck + 2);

        const uint32_t as0 = smem_u32(As + (ck % NSTG) * HTSZ);
        const uint32_t bs0 = smem_u32(Bs + (ck % NSTG) * HTSZ);
#pragma unroll
        for (int k0 = 0; k0 < GBK; k0 += 16) {
            uint32_t bf[4][2];
#pragma unroll
            for (int np = 0; np < 2; np++) {
                const uint32_t addr =
                    bs0 + 2 * (b_loff + (wc * 32 + np * 16) * SH + k0);
                ldsm_x4(bf[2 * np][0], bf[2 * np][1],
                        bf[2 * np + 1][0], bf[2 * np + 1][1], addr);
            }
#pragma unroll
            for (int mt = 0; mt < 4; mt++) {
                uint32_t a0, a1, a2, a3;
                const uint32_t addr =
                    as0 + 2 * (a_loff + (wr * 64 + mt * 16) * SH + k0);
                ldsm_x4(a0, a1, a2, a3, addr);
#pragma unroll
                for (int nt = 0; nt < 4; nt++)
                    mma_f16(acc[mt][nt][0], acc[mt][nt][1],
                            acc[mt][nt][2], acc[mt][nt][3],
                            a0, a1, a2, a3, bf[nt][0], bf[nt][1]);
            }
        }
    }

    // epilogue
#pragma unroll
    for (int mt = 0; mt < 4; mt++) {
        const int row0 = bm + wr * 64 + mt * 16 + gid;
#pragma unroll
        for (int nt = 0; nt < 4; nt++) {
            const int col = bn + wc * 32 + nt * 8 + tig * 2;
            const float b0 = bias[col], b1 = bias[col + 1];
            if (mode == 0) {
                __half2 v0 = __floats2half2_rn(acc[mt][nt][0] + b0, acc[mt][nt][1] + b1);
                __half2 v1 = __floats2half2_rn(acc[mt][nt][2] + b0, acc[mt][nt][3] + b1);
                *(__half2*)&g_qkv16[(size_t)row0 * N + col] = v0;
                *(__half2*)&g_qkv16[(size_t)(row0 + 8) * N + col] = v1;
            } else {
                float2 v0 = make_float2(acc[mt][nt][0] + b0, acc[mt][nt][1] + b1);
                float2 v1 = make_float2(acc[mt][nt][2] + b0, acc[mt][nt][3] + b1);
                *(float2*)&C_[(size_t)row0 * N + col] = v0;
                *(float2*)&C_[(size_t)(row0 + 8) * N + col] = v1;
            }
        }
    }
}

// ================= fp16 tensor-core flash attention ========================
// CTA = 64 q rows of one (b,h), 4 warps. BKV = 64. All-fp16 operands,
// fp32 accum. K frags: ldmatrix.x4; V frags: ldmatrix.x4.trans.
#define KSTR 72                     // halves per smem row (144 B, 9l%8 pattern)
#define KTILE (64 * KSTR)           // halves per K or V tile
#define FLASH_SMEM (4 * KTILE * 2 + 512)   // 37376 B

__global__ void __launch_bounds__(128)
flash_h(const int* __restrict__ amask)
{
    extern __shared__ __half hsm[];
    const int qb = 31 - (int)blockIdx.x;     // heavy blocks first
    const int h  = blockIdx.y;
    const int b  = blockIdx.z;
    const int t  = threadIdx.x;
    const int wid = t >> 5, lane = t & 31;
    const int g = lane >> 2, tg = lane & 3;

    __half* const kbuf[2] = { hsm,             hsm + 2 * KTILE };
    __half* const vbuf[2] = { hsm + KTILE,     hsm + 3 * KTILE };
    float*  const msb     = (float*)(hsm + 4 * KTILE);   // [2][64]

    // ---- Q fragments (fp16, pre-scaled by 1/8) ----
    const int qrlo = qb * 64 + wid * 16 + g;
    const __half* qlo = g_qkv16 + ((size_t)(b * S_LEN) + qrlo) * 3072 + h * 64;
    const __half* qhi = qlo + (size_t)8 * 3072;
    const __half2 sc2 = __floats2half2_rn(0.125f, 0.125f);
    uint32_t qf[4][4];
#pragma unroll
    for (int kk = 0; kk < 4; kk++) {
        __half2 v0 = __hmul2(*(const __half2*)&qlo[16 * kk + 2 * tg], sc2);
        __half2 v1 = __hmul2(*(const __half2*)&qhi[16 * kk + 2 * tg], sc2);
        __half2 v2 = __hmul2(*(const __half2*)&qlo[16 * kk + 2 * tg + 8], sc2);
        __half2 v3 = __hmul2(*(const __half2*)&qhi[16 * kk + 2 * tg + 8], sc2);
        qf[kk][0] = *(uint32_t*)&v0; qf[kk][1] = *(uint32_t*)&v1;
        qf[kk][2] = *(uint32_t*)&v2; qf[kk][3] = *(uint32_t*)&v3;
    }

    // ldmatrix lane offsets (halves)
    const int kf_loff = ((lane & 7) + ((lane >> 4) & 1) * 8) * KSTR
                        + ((lane >> 3) & 1) * 8;          // K (non-trans, B-style)
    const int vf_loff = (lane & 15) * KSTR + ((lane >> 4) & 1) * 8;  // V (trans)

    float oa[8][4];
#pragma unroll
    for (int j = 0; j < 8; j++)
#pragma unroll
        for (int i = 0; i < 4; i++) oa[j][i] = 0.f;
    float m0 = -1e30f, m1 = -1e30f, l0 = 0.f, l1 = 0.f;

    auto issue = [&](int jt) {
        const int buf = jt & 1;
        __half* ks = kbuf[buf];
        __half* vs = vbuf[buf];
        const int j0 = jt * 64;
#pragma unroll
        for (int u = 0; u < 4; u++) {
            const int idx = t + 128 * u;           // 0..511
            const int r = idx >> 3, c8 = (idx & 7) * 8;
            const __half* src = g_qkv16 + ((size_t)(b * S_LEN) + j0 + r) * 3072
                                + 1024 + h * 64 + c8;
            cp_async16(smem_u32(ks + r * KSTR + c8), src);
            cp_async16(smem_u32(vs + r * KSTR + c8), src + 1024);
        }
        if (t < 64)
            msb[buf * 64 + t] = amask[b * S_LEN + j0 + t] ? 0.f : NEG;
        cp_commit();
    };

    issue(0);

    for (int jt = 0; jt <= qb; jt++) {
        if (jt < qb) { issue(jt + 1); cp_wait1(); }
        else         { cp_wait0(); }
        __syncthreads();

        const int buf = jt & 1;
        const uint32_t ks0 = smem_u32(kbuf[buf]);
        const uint32_t vs0 = smem_u32(vbuf[buf]);
        const float*   mb  = msb + buf * 64;

        // ---- S = Q K^T (fp16 mma, fp32 accum) ----
        float sc[8][4];
#pragma unroll
        for (int j = 0; j < 8; j++)
#pragma unroll
            for (int i = 0; i < 4; i++) sc[j][i] = 0.f;
#pragma unroll
        for (int kk = 0; kk < 4; kk++) {
            uint32_t kf[8][2];
#pragma unroll
            for (int nb = 0; nb < 4; nb++) {
                const uint32_t addr =
                    ks0 + 2 * (kf_loff + nb * 16 * KSTR + kk * 16);
                ldsm_x4(kf[2 * nb][0], kf[2 * nb][1],
                        kf[2 * nb + 1][0], kf[2 * nb + 1][1], addr);
            }
#pragma unroll
            for (int j = 0; j < 8; j++)
                mma_f16(sc[j][0], sc[j][1], sc[j][2], sc[j][3],
                        qf[kk][0], qf[kk][1], qf[kk][2], qf[kk][3],
                        kf[j][0], kf[j][1]);
        }

        // ---- masks + online softmax ----
        const bool diag = (jt == qb);
        const int rlo = wid * 16 + g, rhi = rlo + 8;
        float tm0 = -1e30f, tm1 = -1e30f;
#pragma unroll
        for (int j = 0; j < 8; j++) {
            const float2 mm = *(const float2*)&mb[8 * j + 2 * tg];
            float c0 = sc[j][0] + mm.x, c1 = sc[j][1] + mm.y;
            float c2 = sc[j][2] + mm.x, c3 = sc[j][3] + mm.y;
            if (diag) {
                const int kv = 8 * j + 2 * tg;
                c0 = (kv     > rlo) ? NEG : c0;
                c1 = (kv + 1 > rlo) ? NEG : c1;
                c2 = (kv     > rhi) ? NEG : c2;
                c3 = (kv + 1 > rhi) ? NEG : c3;
            }
            sc[j][0] = c0; sc[j][1] = c1; sc[j][2] = c2; sc[j][3] = c3;
            tm0 = fmaxf(tm0, fmaxf(c0, c1));
            tm1 = fmaxf(tm1, fmaxf(c2, c3));
        }
        tm0 = fmaxf(tm0, __shfl_xor_sync(0xffffffffu, tm0, 1));
        tm0 = fmaxf(tm0, __shfl_xor_sync(0xffffffffu, tm0, 2));
        tm1 = fmaxf(tm1, __shfl_xor_sync(0xffffffffu, tm1, 1));
        tm1 = fmaxf(tm1, __shfl_xor_sync(0xffffffffu, tm1, 2));

        const float mn0 = fmaxf(m0, tm0), mn1 = fmaxf(m1, tm1);
        const float al0 = __expf(m0 - mn0), al1 = __expf(m1 - mn1);
        float s0 = 0.f, s1 = 0.f;
#pragma unroll
        for (int j = 0; j < 8; j++) {
            sc[j][0] = __expf(sc[j][0] - mn0);
            sc[j][1] = __expf(sc[j][1] - mn0);
            sc[j][2] = __expf(sc[j][2] - mn1);
            sc[j][3] = __expf(sc[j][3] - mn1);
            s0 += sc[j][0] + sc[j][1];
            s1 += sc[j][2] + sc[j][3];
        }
        s0 += __shfl_xor_sync(0xffffffffu, s0, 1);
        s0 += __shfl_xor_sync(0xffffffffu, s0, 2);
        s1 += __shfl_xor_sync(0xffffffffu, s1, 1);
        s1 += __shfl_xor_sync(0xffffffffu, s1, 2);
        l0 = l0 * al0 + s0; l1 = l1 * al1 + s1;
        m0 = mn0; m1 = mn1;
#pragma unroll
        for (int j = 0; j < 8; j++) {
            oa[j][0] *= al0; oa[j][1] *= al0;
            oa[j][2] *= al1; oa[j][3] *= al1;
        }

        // ---- O += P V (V frags via ldmatrix.trans) ----
#pragma unroll
        for (int kk = 0; kk < 4; kk++) {
            const uint32_t a0 = packh2(sc[2 * kk][0],     sc[2 * kk][1]);
            const uint32_t a1 = packh2(sc[2 * kk][2],     sc[2 * kk][3]);
            const uint32_t a2 = packh2(sc[2 * kk + 1][0], sc[2 * kk + 1][1]);
            const uint32_t a3 = packh2(sc[2 * kk + 1][2], sc[2 * kk + 1][3]);
#pragma unroll
            for (int db = 0; db < 4; db++) {
                uint32_t b00, b01, b10, b11;
                const uint32_t addr =
                    vs0 + 2 * (vf_loff + kk * 16 * KSTR + db * 16);
                ldsm_x4_t(b00, b01, b10, b11, addr);
                mma_f16(oa[2 * db][0], oa[2 * db][1], oa[2 * db][2], oa[2 * db][3],
                        a0, a1, a2, a3, b00, b01);
                mma_f16(oa[2 * db + 1][0], oa[2 * db + 1][1],
                        oa[2 * db + 1][2], oa[2 * db + 1][3],
                        a0, a1, a2, a3, b10, b11);
            }
        }
        __syncthreads();
    }

    // ---- epilogue -> fp16 ctx ----
    const float i0 = 1.f / l0, i1 = 1.f / l1;
    __half2* olo = (__half2*)(g_ctx16 + ((size_t)(b * S_LEN) + qrlo) * EMB + h * 64);
    __half2* ohi = (__half2*)((__half*)olo + (size_t)8 * EMB);
#pragma unroll
    for (int j2 = 0; j2 < 8; j2++) {
        const int d2 = 4 * j2 + tg;
        olo[d2] = __floats2half2_rn(oa[j2][0] * i0, oa[j2][1] * i0);
        ohi[d2] = __floats2half2_rn(oa[j2][2] * i1, oa[j2][3] * i1);
    }
}

// =============================== Launch ====================================
extern "C" void kernel_launch(void* const* d_in, const int* in_sizes, int n_in,
                              void* d_out, int out_size)
{
    const float* X     = (const float*)d_in[0];
    const int*   amask = (const int*)  d_in[1];
    const float* Wa    = (const float*)d_in[2];
    const float* ba    = (const float*)d_in[3];
    const float* Wp    = (const float*)d_in[4];
    const float* bp    = (const float*)d_in[5];
    float* out = (float*)d_out;

    cudaFuncSetAttribute(gemm_h, cudaFuncAttributeMaxDynamicSharedMemorySize,
                         GEMM_SMEM);
    cudaFuncSetAttribute(flash_h, cudaFuncAttributeMaxDynamicSharedMemorySize,
                         FLASH_SMEM);

    // 0) convert inputs to fp16
    {
        const int nx = MTOT * EMB / 4, na = 3 * EMB * EMB / 4, np = EMB * EMB / 4;
        cvt_f2h<<<(nx + 255) / 256, 256>>>((const float4*)X, nx, 0);
        cvt_f2h<<<(na + 255) / 256, 256>>>((const float4*)Wa, na, 1);
        cvt_f2h<<<(np + 255) / 256, 256>>>((const float4*)Wp, np, 2);
    }
    // 1) qkv = X @ Wa^T + ba -> g_qkv16 (fp16)
    {
        dim3 grid(3 * EMB / GBN, MTOT / GBM);
        gemm_h<<<grid, 256, GEMM_SMEM>>>(0, ba, nullptr, MTOT, 3 * EMB, EMB);
    }
    // 2) attention -> g_ctx16 (fp16)
    {
        dim3 grid(S_LEN / 64, NH, BATCH);
        flash_h<<<grid, 128, FLASH_SMEM>>>(amask);
    }
    // 3) out = ctx @ Wp^T + bp (fp32)
    {
        dim3 grid(EMB / GBN, MTOT / GBM);
        gemm_h<<<grid, 256, GEMM_SMEM>>>(1, bp, out, MTOT, EMB, EMB);
    }
}